// round 2
// baseline (speedup 1.0000x reference)
#include <cuda_runtime.h>
#include <math.h>

// Problem constants
#define BB   4
#define SS   4096
#define DD   1024
#define HH   16
#define KK   64
#define MR   (BB*SS)          // 16384 rows
#define SEG  256
#define NSEG (SS/SEG)         // 16

// ---------------- scratch (static device globals; no runtime alloc) -------
__device__ float g_att[(size_t)BB*SS*HH];        // logits -> att weights (1 MB)
__device__ float g_v[(size_t)MR*DD];             // v / attn_out in place (64 MB)
__device__ float g_seg[(size_t)BB*NSEG*DD];      // segment sums (256 KB)
__device__ float g_op[(size_t)MR*DD];            // operator output (64 MB)
__device__ float g_h1[(size_t)MR*DD];            // ff1 hidden (64 MB)

// ---------------- attention logits: (B,S,D) @ (D,H) -> (B,S,H) -----------
__global__ void k_logits(const float* __restrict__ inputs,
                         const float* __restrict__ W,
                         float* __restrict__ logits) {
    __shared__ float row[DD];
    int r = blockIdx.x;
    const float* x = inputs + (size_t)r * DD;
    for (int i = threadIdx.x; i < DD; i += 256) row[i] = x[i];
    __syncthreads();
    int w = threadIdx.x >> 5, lane = threadIdx.x & 31;
    for (int h = w; h < HH; h += 8) {
        float s = 0.f;
        for (int i = lane; i < DD; i += 32) s += row[i] * W[i * HH + h];
        #pragma unroll
        for (int o = 16; o > 0; o >>= 1) s += __shfl_xor_sync(0xffffffffu, s, o);
        if (lane == 0) logits[(size_t)r * HH + h] = s;
    }
}

// ------------- per (b,h): max over S, then att = exp((x-max)*temp) -------
__global__ void k_att_norm(float* __restrict__ logits, const float* __restrict__ temp) {
    int b = blockIdx.x >> 4, h = blockIdx.x & 15;
    float* p = logits + (size_t)b * SS * HH + h;
    float m = -3.4e38f;
    for (int s = threadIdx.x; s < SS; s += 256) m = fmaxf(m, p[(size_t)s * HH]);
    __shared__ float red[256];
    red[threadIdx.x] = m; __syncthreads();
    for (int o = 128; o > 0; o >>= 1) {
        if (threadIdx.x < o) red[threadIdx.x] = fmaxf(red[threadIdx.x], red[threadIdx.x + o]);
        __syncthreads();
    }
    m = red[0];
    float t = temp[h];
    for (int s = threadIdx.x; s < SS; s += 256) {
        size_t idx = (size_t)s * HH;
        p[idx] = expf((p[idx] - m) * t);
    }
}

// ---------------- segmented scan over S --------------------------------
// pass 1: per-segment channel sums
__global__ void k_scan1(const float* __restrict__ V, float* __restrict__ segsum) {
    int c = blockIdx.x * 128 + threadIdx.x;
    int seg = blockIdx.y, b = blockIdx.z;
    const float* p = V + ((size_t)b * SS + (size_t)seg * SEG) * DD + c;
    float s = 0.f;
    #pragma unroll 4
    for (int i = 0; i < SEG; i++) s += p[(size_t)i * DD];
    segsum[((size_t)b * NSEG + seg) * DD + c] = s;
}

// pass 2: exclusive scan of segment sums (in place)
__global__ void k_scan2(float* __restrict__ segsum) {
    int b = blockIdx.x, c = threadIdx.x;
    float run = 0.f;
    for (int seg = 0; seg < NSEG; seg++) {
        size_t idx = ((size_t)b * NSEG + seg) * DD + c;
        float v = segsum[idx];
        segsum[idx] = run;
        run += v;
    }
}

// pass 3: prefix + att scaling, write attn_out in place over V
__global__ void k_scan3(float* __restrict__ V, const float* __restrict__ segsum,
                        const float* __restrict__ att) {
    int c = blockIdx.x * 128 + threadIdx.x;
    int seg = blockIdx.y, b = blockIdx.z;
    int h = c >> 6;
    float run = segsum[((size_t)b * NSEG + seg) * DD + c];
    size_t base = (size_t)b * SS + (size_t)seg * SEG;
    float* p = V + base * DD + c;
    const float* ap = att + base * HH + h;
    #pragma unroll 4
    for (int i = 0; i < SEG; i++) {
        run += p[(size_t)i * DD];
        float a = ap[(size_t)i * HH];
        float cnt = (float)(seg * SEG + i + 1);
        p[(size_t)i * DD] = a * run / (a * cnt + 1e-30f);
    }
}

// ---------------- tiled SGEMM: C = A(MxK) * B(KxN) + epilogue -----------
// MODE 0: C = AB
// MODE 1: C = AB + aux[(row>>12)*N + col]          (per-batch vector)
// MODE 2: C = relu(AB + C + bias[col])             (accumulate + bias + relu)
// MODE 3: C = AB + bias[col] + aux[row*N + col]    (bias + residual)
template<int MODE>
__global__ void __launch_bounds__(256)
sgemm128(const float* __restrict__ A, const float* __restrict__ Bm,
         float* __restrict__ C, int M, int N, int Kd,
         const float* __restrict__ aux, const float* __restrict__ bias) {
    __shared__ float As[8][128];
    __shared__ float Bs[8][128];
    int tid = threadIdx.x;
    int m0 = blockIdx.y * 128, n0 = blockIdx.x * 128;
    int arow = tid >> 1, acol = (tid & 1) * 4;
    int brow = tid >> 5, bcol = (tid & 31) * 4;
    int tx = tid & 15, ty = tid >> 4;

    float acc[8][8];
    #pragma unroll
    for (int i = 0; i < 8; i++)
        #pragma unroll
        for (int j = 0; j < 8; j++) acc[i][j] = 0.f;

    const float* Aptr = A + (size_t)(m0 + arow) * Kd + acol;
    const float* Bptr = Bm + (size_t)brow * N + n0 + bcol;

    for (int k0 = 0; k0 < Kd; k0 += 8) {
        float4 av = *(const float4*)(Aptr + k0);
        float4 bv = *(const float4*)(Bptr + (size_t)k0 * N);
        __syncthreads();
        As[acol + 0][arow] = av.x;
        As[acol + 1][arow] = av.y;
        As[acol + 2][arow] = av.z;
        As[acol + 3][arow] = av.w;
        *(float4*)&Bs[brow][bcol] = bv;
        __syncthreads();
        #pragma unroll
        for (int kk = 0; kk < 8; kk++) {
            float4 a0 = *(const float4*)&As[kk][ty * 8];
            float4 a1 = *(const float4*)&As[kk][ty * 8 + 4];
            float4 b0 = *(const float4*)&Bs[kk][tx * 8];
            float4 b1 = *(const float4*)&Bs[kk][tx * 8 + 4];
            float a[8] = {a0.x, a0.y, a0.z, a0.w, a1.x, a1.y, a1.z, a1.w};
            float b[8] = {b0.x, b0.y, b0.z, b0.w, b1.x, b1.y, b1.z, b1.w};
            #pragma unroll
            for (int i = 0; i < 8; i++)
                #pragma unroll
                for (int j = 0; j < 8; j++)
                    acc[i][j] = fmaf(a[i], b[j], acc[i][j]);
        }
    }

    int col0 = n0 + tx * 8;
    #pragma unroll
    for (int i = 0; i < 8; i++) {
        int row = m0 + ty * 8 + i;
        float* cp = C + (size_t)row * N + col0;
        float out[8];
        #pragma unroll
        for (int j = 0; j < 8; j++) out[j] = acc[i][j];
        if (MODE == 1) {
            const float* vp = aux + (size_t)(row >> 12) * N + col0;
            #pragma unroll
            for (int j = 0; j < 8; j++) out[j] += vp[j];
        }
        if (MODE == 2) {
            #pragma unroll
            for (int j = 0; j < 8; j++)
                out[j] = fmaxf(out[j] + cp[j] + bias[col0 + j], 0.f);
        }
        if (MODE == 3) {
            const float* rp = aux + (size_t)row * N + col0;
            #pragma unroll
            for (int j = 0; j < 8; j++) out[j] += bias[col0 + j] + rp[j];
        }
        *(float4*)cp       = make_float4(out[0], out[1], out[2], out[3]);
        *(float4*)(cp + 4) = make_float4(out[4], out[5], out[6], out[7]);
    }
}

// ---------------- LayerNorm (in place over d_out rows) ------------------
__global__ void k_ln(float* __restrict__ X, const float* __restrict__ g,
                     const float* __restrict__ be) {
    int r = blockIdx.x;
    float* p = X + (size_t)r * DD;
    int i = threadIdx.x * 4;
    float4 x = *(const float4*)(p + i);
    __shared__ float red[256];
    float s = x.x + x.y + x.z + x.w;
    red[threadIdx.x] = s; __syncthreads();
    for (int o = 128; o > 0; o >>= 1) {
        if (threadIdx.x < o) red[threadIdx.x] += red[threadIdx.x + o];
        __syncthreads();
    }
    float mean = red[0] * (1.f / DD);
    __syncthreads();
    float d0 = x.x - mean, d1 = x.y - mean, d2 = x.z - mean, d3 = x.w - mean;
    red[threadIdx.x] = d0 * d0 + d1 * d1 + d2 * d2 + d3 * d3;
    __syncthreads();
    for (int o = 128; o > 0; o >>= 1) {
        if (threadIdx.x < o) red[threadIdx.x] += red[threadIdx.x + o];
        __syncthreads();
    }
    float inv = rsqrtf(red[0] * (1.f / DD) + 1e-6f);
    float4 o4;
    o4.x = d0 * inv * g[i + 0] + be[i + 0];
    o4.y = d1 * inv * g[i + 1] + be[i + 1];
    o4.z = d2 * inv * g[i + 2] + be[i + 2];
    o4.w = d3 * inv * g[i + 3] + be[i + 3];
    *(float4*)(p + i) = o4;
}

// ---------------- launcher ----------------------------------------------
extern "C" void kernel_launch(void* const* d_in, const int* in_sizes, int n_in,
                              void* d_out, int out_size) {
    (void)in_sizes; (void)n_in; (void)out_size;
    const float* inputs   = (const float*)d_in[0];
    const float* vector   = (const float*)d_in[1];
    const float* attw     = (const float*)d_in[2];
    const float* temp     = (const float*)d_in[3];
    const float* values   = (const float*)d_in[4];
    const float* oper     = (const float*)d_in[5];
    const float* ff1      = (const float*)d_in[6];
    const float* ff1_bias = (const float*)d_in[7];
    const float* ff2      = (const float*)d_in[8];
    const float* ff2_bias = (const float*)d_in[9];
    const float* ln_gamma = (const float*)d_in[10];
    const float* ln_beta  = (const float*)d_in[11];
    float* out = (float*)d_out;

    float *att_p, *v_p, *seg_p, *op_p, *h1_p;
    cudaGetSymbolAddress((void**)&att_p, g_att);
    cudaGetSymbolAddress((void**)&v_p,   g_v);
    cudaGetSymbolAddress((void**)&seg_p, g_seg);
    cudaGetSymbolAddress((void**)&op_p,  g_op);
    cudaGetSymbolAddress((void**)&h1_p,  g_h1);

    dim3 gemmGrid(DD / 128, MR / 128);   // (8, 128)

    // attention weights
    k_logits<<<MR, 256>>>(inputs, attw, att_p);
    k_att_norm<<<BB * HH, 256>>>(att_p, temp);

    // v = inputs @ values
    sgemm128<0><<<gemmGrid, 256>>>(inputs, values, v_p, MR, DD, DD, nullptr, nullptr);

    // causal cumsum + att scaling (attn_out in place over v)
    dim3 scanGrid(DD / 128, NSEG, BB);
    k_scan1<<<scanGrid, 128>>>(v_p, seg_p);
    k_scan2<<<BB, DD>>>(seg_p);
    k_scan3<<<scanGrid, 128>>>(v_p, seg_p, att_p);

    // op = attn_out @ operator + vector[b]
    sgemm128<1><<<gemmGrid, 256>>>(v_p, oper, op_p, MR, DD, DD, vector, nullptr);

    // h1 = relu(inputs @ ff1_top + op @ ff1_bot + b1)
    sgemm128<0><<<gemmGrid, 256>>>(inputs, ff1, h1_p, MR, DD, DD, nullptr, nullptr);
    sgemm128<2><<<gemmGrid, 256>>>(op_p, ff1 + (size_t)DD * DD, h1_p, MR, DD, DD,
                                   nullptr, ff1_bias);

    // res = h1 @ ff2 + b2 + inputs  (written straight to d_out)
    sgemm128<3><<<gemmGrid, 256>>>(h1_p, ff2, out, MR, DD, DD, inputs, ff2_bias);

    // LayerNorm in place
    k_ln<<<MR, 256>>>(out, ln_gamma, ln_beta);
}

// round 5
// speedup vs baseline: 3.0459x; 3.0459x over previous
#include <cuda_runtime.h>
#include <math.h>
#include <stdint.h>

// Problem constants
#define BB   4
#define SS   4096
#define DD   1024
#define HH   16
#define MR   (BB*SS)          // 16384 rows
#define SEG  128
#define NSEG (SS/SEG)         // 32

#define KC   16               // K per pipeline chunk
#define KCP  20               // padded floats per SMEM row (conflict-free)

// ---------------- scratch (static device globals) ------------------------
__device__ float g_att[(size_t)BB*SS*HH];        // att weights (1 MB)
__device__ float g_v[(size_t)MR*DD];             // v / attn_out in place (64 MB)
__device__ float g_seg[(size_t)BB*NSEG*DD];      // segment sums
__device__ float g_h1[(size_t)MR*DD];            // ff1 hidden (64 MB)
__device__ float g_inr[(size_t)MR*DD];           // tf32-rounded inputs (64 MB)
__device__ float g_valT[(size_t)DD*DD];          // values^T   [N,K] tf32
__device__ float g_f1tT[(size_t)DD*DD];          // ff1_top^T  [N,K] tf32
__device__ float g_t1  [(size_t)DD*DD];          // ff1_bot^T  [D,DV] tf32
__device__ float g_ff2T[(size_t)DD*DD];          // ff2^T      [N,K] tf32
__device__ float g_operr[(size_t)DD*DD];         // operator tf32-rounded
__device__ float g_owT [(size_t)DD*DD];          // owT[n][f] tf32
__device__ float g_vb  [(size_t)BB*DD];          // vector@ff1_bot + b1

// =================== helpers =============================================
__device__ __forceinline__ float to_tf32(float x) {
    uint32_t o;
    asm("cvt.rna.tf32.f32 %0, %1;" : "=r"(o) : "r"(__float_as_uint(x)));
    return __uint_as_float(o);
}
__device__ __forceinline__ uint32_t smem_u32(const void* p) {
    uint32_t a;
    asm("{ .reg .u64 t; cvta.to.shared.u64 t, %1; cvt.u32.u64 %0, t; }"
        : "=r"(a) : "l"(p));
    return a;
}
__device__ __forceinline__ void cp16(uint32_t s, const void* g) {
    asm volatile("cp.async.cg.shared.global [%0], [%1], 16;"
                 :: "r"(s), "l"(g) : "memory");
}
__device__ __forceinline__ void cp_commit() {
    asm volatile("cp.async.commit_group;" ::: "memory");
}
template<int N>
__device__ __forceinline__ void cp_wait() {
    asm volatile("cp.async.wait_group %0;" :: "n"(N) : "memory");
}

__device__ __forceinline__ void mma8(float* d, const float* a, const float* b) {
    asm volatile(
        "mma.sync.aligned.m16n8k8.row.col.f32.tf32.tf32.f32 "
        "{%0,%1,%2,%3}, {%4,%5,%6,%7}, {%8,%9}, {%0,%1,%2,%3};"
        : "+f"(d[0]), "+f"(d[1]), "+f"(d[2]), "+f"(d[3])
        : "r"(__float_as_uint(a[0])), "r"(__float_as_uint(a[1])),
          "r"(__float_as_uint(a[2])), "r"(__float_as_uint(a[3])),
          "r"(__float_as_uint(b[0])), "r"(__float_as_uint(b[1])));
}

// =================== tf32 mma.sync GEMM ==================================
// C[m,n] = sum_k A1[m,k]*B1[n,k] (+ A2[m,k]*B2[n,k] if A2), K=1024 per pair.
// MODE 0: C = acc                       (fp32 out)
// MODE 1: C = tf32(acc)                 (rounded out, for OW)
// MODE 2: C = tf32(relu(acc + aux2[(row>>12)*DD + col]))
// MODE 3: C = acc + aux1[row*DD+col] + aux2[col]
template<int MODE>
__global__ void __launch_bounds__(256, 2)
gemm_mma(const float* __restrict__ A1, const float* __restrict__ B1,
         const float* __restrict__ A2, const float* __restrict__ B2,
         float* __restrict__ C,
         const float* __restrict__ aux1, const float* __restrict__ aux2) {
    __shared__ float As[2][128 * KCP];
    __shared__ float Bs[2][128 * KCP];

    const int tid = threadIdx.x, lane = tid & 31, wid = tid >> 5;
    const int wm = (wid & 3) * 32, wn = (wid >> 2) * 64;
    const int m0 = blockIdx.y * 128, n0 = blockIdx.x * 128;
    const int r4 = lane >> 2, l4 = lane & 3;

    const int nch = A2 ? 128 : 64;

    // per-thread load slots: row = tid>>1, two float4s at k offsets
    const int lrow = tid >> 1;
    const int lk0  = (tid & 1) * 8;   // floats

    float acc[2][8][4];
    #pragma unroll
    for (int i = 0; i < 2; i++)
        #pragma unroll
        for (int j = 0; j < 8; j++)
            #pragma unroll
            for (int q = 0; q < 4; q++) acc[i][j][q] = 0.f;

    auto load_chunk = [&](int c) {
        const float* Ap = (c < 64) ? A1 : A2;
        const float* Bp = (c < 64) ? B1 : B2;
        int k0 = (c & 63) * KC;
        int buf = c & 1;
        const float* ga = Ap + (size_t)(m0 + lrow) * DD + k0 + lk0;
        const float* gb = Bp + (size_t)(n0 + lrow) * DD + k0 + lk0;
        uint32_t sa = smem_u32(&As[buf][lrow * KCP + lk0]);
        uint32_t sb = smem_u32(&Bs[buf][lrow * KCP + lk0]);
        cp16(sa, ga);
        cp16(sa + 16, ga + 4);
        cp16(sb, gb);
        cp16(sb + 16, gb + 4);
        cp_commit();
    };

    load_chunk(0);
    for (int c = 0; c < nch; c++) {
        if (c + 1 < nch) { load_chunk(c + 1); cp_wait<1>(); }
        else             { cp_wait<0>(); }
        __syncthreads();

        int buf = c & 1;
        const float* as = As[buf];
        const float* bs = Bs[buf];
        #pragma unroll
        for (int ks = 0; ks < 2; ks++) {
            float a[2][4];
            float b[8][2];
            #pragma unroll
            for (int i = 0; i < 2; i++) {
                int mrow = wm + i * 16 + r4;
                a[i][0] = as[mrow * KCP + ks * 8 + l4];
                a[i][1] = as[(mrow + 8) * KCP + ks * 8 + l4];
                a[i][2] = as[mrow * KCP + ks * 8 + l4 + 4];
                a[i][3] = as[(mrow + 8) * KCP + ks * 8 + l4 + 4];
            }
            #pragma unroll
            for (int j = 0; j < 8; j++) {
                int nrow = wn + j * 8 + r4;
                b[j][0] = bs[nrow * KCP + ks * 8 + l4];
                b[j][1] = bs[nrow * KCP + ks * 8 + l4 + 4];
            }
            #pragma unroll
            for (int i = 0; i < 2; i++)
                #pragma unroll
                for (int j = 0; j < 8; j++)
                    mma8(acc[i][j], a[i], b[j]);
        }
        __syncthreads();
    }

    // epilogue
    #pragma unroll
    for (int i = 0; i < 2; i++) {
        int grow = m0 + wm + i * 16 + r4;
        #pragma unroll
        for (int j = 0; j < 8; j++) {
            int gcol = n0 + wn + j * 8 + l4 * 2;
            float v0 = acc[i][j][0], v1 = acc[i][j][1];
            float v2 = acc[i][j][2], v3 = acc[i][j][3];
            if (MODE == 1) {
                v0 = to_tf32(v0); v1 = to_tf32(v1);
                v2 = to_tf32(v2); v3 = to_tf32(v3);
            }
            if (MODE == 2) {
                const float* vb0 = aux2 + (size_t)(grow >> 12) * DD + gcol;
                const float* vb1 = aux2 + (size_t)((grow + 8) >> 12) * DD + gcol;
                v0 = to_tf32(fmaxf(v0 + vb0[0], 0.f));
                v1 = to_tf32(fmaxf(v1 + vb0[1], 0.f));
                v2 = to_tf32(fmaxf(v2 + vb1[0], 0.f));
                v3 = to_tf32(fmaxf(v3 + vb1[1], 0.f));
            }
            if (MODE == 3) {
                const float* rp0 = aux1 + (size_t)grow * DD + gcol;
                const float* rp1 = aux1 + (size_t)(grow + 8) * DD + gcol;
                v0 += rp0[0] + aux2[gcol];
                v1 += rp0[1] + aux2[gcol + 1];
                v2 += rp1[0] + aux2[gcol];
                v3 += rp1[1] + aux2[gcol + 1];
            }
            *(float2*)(C + (size_t)grow * DD + gcol)       = make_float2(v0, v1);
            *(float2*)(C + (size_t)(grow + 8) * DD + gcol) = make_float2(v2, v3);
        }
    }
}

// =================== transpose 1024x1024 + tf32 round ====================
__global__ void k_transpose(const float* __restrict__ src, float* __restrict__ dst) {
    __shared__ float t[32][33];
    int c0 = blockIdx.x * 32, r0 = blockIdx.y * 32;
    int x = threadIdx.x, y = threadIdx.y;
    #pragma unroll
    for (int j = 0; j < 32; j += 8)
        t[y + j][x] = src[(size_t)(r0 + y + j) * DD + c0 + x];
    __syncthreads();
    #pragma unroll
    for (int j = 0; j < 32; j += 8)
        dst[(size_t)(c0 + y + j) * DD + r0 + x] = to_tf32(t[x][y + j]);
}

// =================== tf32-rounded copy ===================================
__global__ void k_round(const float* __restrict__ src, float* __restrict__ dst,
                        int n4) {
    int i = blockIdx.x * 256 + threadIdx.x;
    if (i < n4) {
        float4 v = ((const float4*)src)[i];
        v.x = to_tf32(v.x); v.y = to_tf32(v.y);
        v.z = to_tf32(v.z); v.w = to_tf32(v.w);
        ((float4*)dst)[i] = v;
    }
}

// =================== vb = vector @ ff1_bot + b1 ==========================
__global__ void k_vb(const float* __restrict__ vec, const float* __restrict__ t1,
                     const float* __restrict__ bias, float* __restrict__ vb) {
    __shared__ float sv[DD];
    int b = blockIdx.y;
    for (int i = threadIdx.x; i < DD; i += 256) sv[i] = vec[(size_t)b * DD + i];
    __syncthreads();
    int d = blockIdx.x * 256 + threadIdx.x;
    const float4* tp = (const float4*)(t1 + (size_t)d * DD);
    const float4* vp = (const float4*)sv;
    float s = 0.f;
    #pragma unroll 4
    for (int i = 0; i < DD / 4; i++) {
        float4 a = tp[i], v = vp[i];
        s += a.x * v.x + a.y * v.y + a.z * v.z + a.w * v.w;
    }
    vb[(size_t)b * DD + d] = s + bias[d];
}

// =================== logits: warp-per-row, W^T in smem ===================
__global__ void k_logits(const float* __restrict__ inputs,
                         const float* __restrict__ W,
                         float* __restrict__ logits) {
    extern __shared__ float Wt[];   // [16][1024]
    int tid = threadIdx.x;
    for (int idx = tid; idx < DD * HH; idx += 256) {
        int i = idx >> 4, h = idx & 15;
        Wt[h * DD + i] = W[idx];
    }
    __syncthreads();
    int warp = tid >> 5, lane = tid & 31;
    for (int rr = 0; rr < 4; rr++) {
        int r = blockIdx.x * 32 + warp * 4 + rr;
        const float4* xp = (const float4*)(inputs + (size_t)r * DD);
        float acc[HH];
        #pragma unroll
        for (int h = 0; h < HH; h++) acc[h] = 0.f;
        #pragma unroll
        for (int j = 0; j < 8; j++) {
            float4 x = xp[lane + 32 * j];
            int i0 = (lane + 32 * j) * 4;
            #pragma unroll
            for (int h = 0; h < HH; h++) {
                float4 w = *(const float4*)&Wt[h * DD + i0];
                acc[h] += x.x * w.x + x.y * w.y + x.z * w.z + x.w * w.w;
            }
        }
        #pragma unroll
        for (int h = 0; h < HH; h++) {
            #pragma unroll
            for (int o = 16; o > 0; o >>= 1)
                acc[h] += __shfl_xor_sync(0xffffffffu, acc[h], o);
        }
        if (lane == 0) {
            #pragma unroll
            for (int h = 0; h < HH; h++) logits[(size_t)r * HH + h] = acc[h];
        }
    }
}

// ------------- per (b,h): max over S, then att = exp((x-max)*temp) -------
__global__ void k_att_norm(float* __restrict__ logits, const float* __restrict__ temp) {
    int b = blockIdx.x >> 4, h = blockIdx.x & 15;
    float* p = logits + (size_t)b * SS * HH + h;
    float m = -3.4e38f;
    for (int s = threadIdx.x; s < SS; s += 256) m = fmaxf(m, p[(size_t)s * HH]);
    __shared__ float red[256];
    red[threadIdx.x] = m; __syncthreads();
    for (int o = 128; o > 0; o >>= 1) {
        if (threadIdx.x < o) red[threadIdx.x] = fmaxf(red[threadIdx.x], red[threadIdx.x + o]);
        __syncthreads();
    }
    m = red[0];
    float t = temp[h];
    for (int s = threadIdx.x; s < SS; s += 256) {
        size_t idx = (size_t)s * HH;
        p[idx] = expf((p[idx] - m) * t);
    }
}

// ---------------- segmented scan over S --------------------------------
__global__ void k_scan1(const float* __restrict__ V, float* __restrict__ segsum) {
    int c = blockIdx.x * 128 + threadIdx.x;
    int seg = blockIdx.y, b = blockIdx.z;
    const float* p = V + ((size_t)b * SS + (size_t)seg * SEG) * DD + c;
    float s = 0.f;
    #pragma unroll 8
    for (int i = 0; i < SEG; i++) s += p[(size_t)i * DD];
    segsum[((size_t)b * NSEG + seg) * DD + c] = s;
}

__global__ void k_scan2(float* __restrict__ segsum) {
    int b = blockIdx.x, c = threadIdx.x;
    float run = 0.f;
    for (int seg = 0; seg < NSEG; seg++) {
        size_t idx = ((size_t)b * NSEG + seg) * DD + c;
        float v = segsum[idx];
        segsum[idx] = run;
        run += v;
    }
}

// prefix + att scaling; output rounded to tf32 (it feeds the next GEMM as A)
__global__ void k_scan3(float* __restrict__ V, const float* __restrict__ segsum,
                        const float* __restrict__ att) {
    int c = blockIdx.x * 128 + threadIdx.x;
    int seg = blockIdx.y, b = blockIdx.z;
    int h = c >> 6;
    float run = segsum[((size_t)b * NSEG + seg) * DD + c];
    size_t base = (size_t)b * SS + (size_t)seg * SEG;
    float* p = V + base * DD + c;
    const float* ap = att + base * HH + h;
    #pragma unroll 8
    for (int i = 0; i < SEG; i++) {
        run += p[(size_t)i * DD];
        float a = ap[(size_t)i * HH];
        float cnt = (float)(seg * SEG + i + 1);
        p[(size_t)i * DD] = to_tf32(a * run / (a * cnt + 1e-30f));
    }
}

// ---------------- LayerNorm (in place over d_out rows) ------------------
__global__ void k_ln(float* __restrict__ X, const float* __restrict__ g,
                     const float* __restrict__ be) {
    int r = blockIdx.x;
    float* p = X + (size_t)r * DD;
    int i = threadIdx.x * 4;
    float4 x = *(const float4*)(p + i);
    __shared__ float red[256];
    float s = x.x + x.y + x.z + x.w;
    red[threadIdx.x] = s; __syncthreads();
    for (int o = 128; o > 0; o >>= 1) {
        if (threadIdx.x < o) red[threadIdx.x] += red[threadIdx.x + o];
        __syncthreads();
    }
    float mean = red[0] * (1.f / DD);
    __syncthreads();
    float d0 = x.x - mean, d1 = x.y - mean, d2 = x.z - mean, d3 = x.w - mean;
    red[threadIdx.x] = d0 * d0 + d1 * d1 + d2 * d2 + d3 * d3;
    __syncthreads();
    for (int o = 128; o > 0; o >>= 1) {
        if (threadIdx.x < o) red[threadIdx.x] += red[threadIdx.x + o];
        __syncthreads();
    }
    float inv = rsqrtf(red[0] * (1.f / DD) + 1e-6f);
    float4 o4;
    o4.x = d0 * inv * g[i + 0] + be[i + 0];
    o4.y = d1 * inv * g[i + 1] + be[i + 1];
    o4.z = d2 * inv * g[i + 2] + be[i + 2];
    o4.w = d3 * inv * g[i + 3] + be[i + 3];
    *(float4*)(p + i) = o4;
}

// ---------------- launcher ----------------------------------------------
extern "C" void kernel_launch(void* const* d_in, const int* in_sizes, int n_in,
                              void* d_out, int out_size) {
    (void)in_sizes; (void)n_in; (void)out_size;
    const float* inputs   = (const float*)d_in[0];
    const float* vector   = (const float*)d_in[1];
    const float* attw     = (const float*)d_in[2];
    const float* temp     = (const float*)d_in[3];
    const float* values   = (const float*)d_in[4];
    const float* oper     = (const float*)d_in[5];
    const float* ff1      = (const float*)d_in[6];
    const float* ff1_bias = (const float*)d_in[7];
    const float* ff2      = (const float*)d_in[8];
    const float* ff2_bias = (const float*)d_in[9];
    const float* ln_gamma = (const float*)d_in[10];
    const float* ln_beta  = (const float*)d_in[11];
    float* out = (float*)d_out;

    float *att_p, *v_p, *seg_p, *h1_p, *inr_p, *valT_p, *f1tT_p, *t1_p, *ff2T_p,
          *operr_p, *owT_p, *vb_p;
    cudaGetSymbolAddress((void**)&att_p,   g_att);
    cudaGetSymbolAddress((void**)&v_p,     g_v);
    cudaGetSymbolAddress((void**)&seg_p,   g_seg);
    cudaGetSymbolAddress((void**)&h1_p,    g_h1);
    cudaGetSymbolAddress((void**)&inr_p,   g_inr);
    cudaGetSymbolAddress((void**)&valT_p,  g_valT);
    cudaGetSymbolAddress((void**)&f1tT_p,  g_f1tT);
    cudaGetSymbolAddress((void**)&t1_p,    g_t1);
    cudaGetSymbolAddress((void**)&ff2T_p,  g_ff2T);
    cudaGetSymbolAddress((void**)&operr_p, g_operr);
    cudaGetSymbolAddress((void**)&owT_p,   g_owT);
    cudaGetSymbolAddress((void**)&vb_p,    g_vb);

    cudaFuncSetAttribute(k_logits, cudaFuncAttributeMaxDynamicSharedMemorySize, 65536);

    dim3 tb(32, 8), tg(32, 32);
    // weight prep: transposes (tf32-rounded) + rounded copies
    k_transpose<<<tg, tb>>>(values, valT_p);
    k_transpose<<<tg, tb>>>(ff1, f1tT_p);
    k_transpose<<<tg, tb>>>(ff1 + (size_t)DD * DD, t1_p);
    k_transpose<<<tg, tb>>>(ff2, ff2T_p);
    k_round<<<(DD * DD / 4 + 255) / 256, 256>>>(oper, operr_p, DD * DD / 4);
    k_round<<<((int)((size_t)MR * DD / 4) + 255) / 256, 256>>>(inputs, inr_p,
                                                               (int)((size_t)MR * DD / 4));

    // vb = vector @ ff1_bot + b1 (full fp32)
    k_vb<<<dim3(DD / 256, BB), 256>>>(vector, t1_p, ff1_bias, vb_p);

    // owT[n][f] = sum_dv t1[n][dv] * operator[f][dv]  (tf32-rounded out)
    gemm_mma<1><<<dim3(8, 8), 256>>>(t1_p, operr_p, nullptr, nullptr,
                                     owT_p, nullptr, nullptr);

    // attention weights
    k_logits<<<MR / 32, 256, 65536>>>(inputs, attw, att_p);
    k_att_norm<<<BB * HH, 256>>>(att_p, temp);

    // v = inputs @ values (fp32 out; rounded later by scan3)
    gemm_mma<0><<<dim3(8, MR / 128), 256>>>(inr_p, valT_p, nullptr, nullptr,
                                            v_p, nullptr, nullptr);

    // causal cumsum + att scaling (attn_out in place over v, tf32 out)
    dim3 scanGrid(DD / 128, NSEG, BB);
    k_scan1<<<scanGrid, 128>>>(v_p, seg_p);
    k_scan2<<<BB, DD>>>(seg_p);
    k_scan3<<<scanGrid, 128>>>(v_p, seg_p, att_p);

    // h1 = relu(inputs@ff1_top + attn@OW + vb)  (dual-K; tf32 out)
    gemm_mma<2><<<dim3(8, MR / 128), 256>>>(inr_p, f1tT_p, v_p, owT_p,
                                            h1_p, nullptr, vb_p);

    // out = h1 @ ff2 + b2 + inputs (fp32)
    gemm_mma<3><<<dim3(8, MR / 128), 256>>>(h1_p, ff2T_p, nullptr, nullptr,
                                            out, inputs, ff2_bias);

    // LayerNorm in place
    k_ln<<<MR, 256>>>(out, ln_gamma, ln_beta);
}

// round 6
// speedup vs baseline: 3.4974x; 1.1483x over previous
#include <cuda_runtime.h>
#include <math.h>
#include <stdint.h>

// Problem constants
#define BB   4
#define SS   4096
#define DD   1024
#define HH   16
#define MR   (BB*SS)          // 16384 rows
#define SEG  128
#define NSEG (SS/SEG)         // 32

#define KCH  32               // K floats per pipeline chunk
#define NST  3                // pipeline stages
#define STF  8192             // floats per stage (A 4096 + B 4096)
#define GEMM_SMEM (NST*STF*4) // 96 KB

// ---------------- scratch (static device globals) ------------------------
__device__ float g_att[(size_t)BB*SS*HH];
__device__ float g_v[(size_t)MR*DD];
__device__ float g_seg[(size_t)BB*NSEG*DD];
__device__ float g_h1[(size_t)MR*DD];
__device__ float g_inr[(size_t)MR*DD];
__device__ float g_valT[(size_t)DD*DD];
__device__ float g_f1tT[(size_t)DD*DD];
__device__ float g_t1  [(size_t)DD*DD];
__device__ float g_ff2T[(size_t)DD*DD];
__device__ float g_operr[(size_t)DD*DD];
__device__ float g_owT [(size_t)DD*DD];
__device__ float g_vb  [(size_t)BB*DD];

// =================== helpers =============================================
__device__ __forceinline__ float to_tf32(float x) {
    uint32_t o;
    asm("cvt.rna.tf32.f32 %0, %1;" : "=r"(o) : "r"(__float_as_uint(x)));
    return __uint_as_float(o);
}
__device__ __forceinline__ uint32_t smem_u32(const void* p) {
    uint32_t a;
    asm("{ .reg .u64 t; cvta.to.shared.u64 t, %1; cvt.u32.u64 %0, t; }"
        : "=r"(a) : "l"(p));
    return a;
}
__device__ __forceinline__ void cp16(uint32_t s, const void* g) {
    asm volatile("cp.async.cg.shared.global [%0], [%1], 16;"
                 :: "r"(s), "l"(g) : "memory");
}
__device__ __forceinline__ void cp_commit() {
    asm volatile("cp.async.commit_group;" ::: "memory");
}
template<int N>
__device__ __forceinline__ void cp_wait() {
    asm volatile("cp.async.wait_group %0;" :: "n"(N) : "memory");
}
__device__ __forceinline__ void ldm_x4(uint32_t* r, uint32_t addr) {
    asm volatile("ldmatrix.sync.aligned.m8n8.x4.shared.b16 {%0,%1,%2,%3}, [%4];"
                 : "=r"(r[0]), "=r"(r[1]), "=r"(r[2]), "=r"(r[3]) : "r"(addr));
}
__device__ __forceinline__ void mma8(float* d, const uint32_t* a, const uint32_t* b) {
    asm volatile(
        "mma.sync.aligned.m16n8k8.row.col.f32.tf32.tf32.f32 "
        "{%0,%1,%2,%3}, {%4,%5,%6,%7}, {%8,%9}, {%0,%1,%2,%3};"
        : "+f"(d[0]), "+f"(d[1]), "+f"(d[2]), "+f"(d[3])
        : "r"(a[0]), "r"(a[1]), "r"(a[2]), "r"(a[3]), "r"(b[0]), "r"(b[1]));
}

// =================== tf32 mma.sync GEMM (ldmatrix + 3-stage) =============
// C[m,n] = sum_k A1[m,k]*B1[n,k] (+ A2[m,k]*B2[n,k] if A2), K=1024 per pair.
// MODE 0: fp32 out    MODE 1: tf32 out
// MODE 2: tf32(relu(acc + aux2[(row>>12)*DD+col]))
// MODE 3: acc + aux1[row*DD+col] + aux2[col]
template<int MODE>
__global__ void __launch_bounds__(256, 2)
gemm_mma(const float* __restrict__ A1, const float* __restrict__ B1,
         const float* __restrict__ A2, const float* __restrict__ B2,
         float* __restrict__ C,
         const float* __restrict__ aux1, const float* __restrict__ aux2) {
    extern __shared__ float sm[];
    const uint32_t sbase = smem_u32(sm);
    const int tid = threadIdx.x, lane = tid & 31, wid = tid >> 5;
    const int wm = (wid & 3) * 32, wn = (wid >> 2) * 64;
    const int m0 = blockIdx.y * 128, n0 = blockIdx.x * 128;
    const int r4 = lane >> 2, l4 = lane & 3;
    const int nch = A2 ? 64 : 32;

    // cp.async mapping: row = tid>>1, chunks (tid&1)*4 .. +3   (chunk = 16B)
    const int lrow = tid >> 1;
    const int lc0  = (tid & 1) * 4;
    const int lr7  = lrow & 7;

    // ldmatrix per-lane row/parity
    const int a_row = wm + (lane & 15);       // + i*16
    const int a_hb  = lane >> 4;
    const int b_rlo = (lane & 7) + ((lane >> 4) & 1) * 8;
    const int b_hb  = (lane >> 3) & 1;

    float acc[2][8][4];
    #pragma unroll
    for (int i = 0; i < 2; i++)
        #pragma unroll
        for (int j = 0; j < 8; j++)
            #pragma unroll
            for (int q = 0; q < 4; q++) acc[i][j][q] = 0.f;

    auto load_chunk = [&](int c) {
        const float* Ap = (c < 32) ? A1 : A2;
        const float* Bp = (c < 32) ? B1 : B2;
        const int k0 = (c & 31) * KCH;
        const uint32_t st = (uint32_t)((c % NST) * STF) * 4u + sbase;
        const float* ga = Ap + (size_t)(m0 + lrow) * DD + k0 + lc0 * 4;
        const float* gb = Bp + (size_t)(n0 + lrow) * DD + k0 + lc0 * 4;
        const uint32_t rowoff = (uint32_t)lrow * 128u;
        #pragma unroll
        for (int q = 0; q < 4; q++) {
            uint32_t sc = (uint32_t)(((lc0 + q) ^ lr7) << 4);
            cp16(st + rowoff + sc,           ga + q * 4);
            cp16(st + 16384u + rowoff + sc,  gb + q * 4);
        }
        cp_commit();
    };

    load_chunk(0);
    load_chunk(1);

    for (int c = 0; c < nch; c++) {
        if (c + 1 < nch) cp_wait<1>(); else cp_wait<0>();
        __syncthreads();

        const uint32_t Ab = sbase + (uint32_t)((c % NST) * STF) * 4u;
        const uint32_t Bb = Ab + 16384u;
        #pragma unroll
        for (int ks = 0; ks < 4; ks++) {
            uint32_t a[2][4], bg[4][4];
            #pragma unroll
            for (int i = 0; i < 2; i++) {
                int row = a_row + i * 16;
                int ch = 2 * ks + a_hb;
                ldm_x4(a[i], Ab + row * 128 + ((ch ^ (row & 7)) << 4));
            }
            #pragma unroll
            for (int g = 0; g < 4; g++) {
                int row = wn + g * 16 + b_rlo;
                int ch = 2 * ks + b_hb;
                ldm_x4(bg[g], Bb + row * 128 + ((ch ^ (row & 7)) << 4));
            }
            #pragma unroll
            for (int i = 0; i < 2; i++)
                #pragma unroll
                for (int j = 0; j < 8; j++)
                    mma8(acc[i][j], a[i], &bg[j >> 1][(j & 1) * 2]);
        }
        __syncthreads();
        if (c + 2 < nch) load_chunk(c + 2);
    }

    // epilogue
    #pragma unroll
    for (int i = 0; i < 2; i++) {
        int grow = m0 + wm + i * 16 + r4;
        #pragma unroll
        for (int j = 0; j < 8; j++) {
            int gcol = n0 + wn + j * 8 + l4 * 2;
            float v0 = acc[i][j][0], v1 = acc[i][j][1];
            float v2 = acc[i][j][2], v3 = acc[i][j][3];
            if (MODE == 1) {
                v0 = to_tf32(v0); v1 = to_tf32(v1);
                v2 = to_tf32(v2); v3 = to_tf32(v3);
            }
            if (MODE == 2) {
                const float* vb0 = aux2 + (size_t)(grow >> 12) * DD + gcol;
                v0 = to_tf32(fmaxf(v0 + vb0[0], 0.f));
                v1 = to_tf32(fmaxf(v1 + vb0[1], 0.f));
                v2 = to_tf32(fmaxf(v2 + vb0[0], 0.f));
                v3 = to_tf32(fmaxf(v3 + vb0[1], 0.f));
            }
            if (MODE == 3) {
                const float* rp0 = aux1 + (size_t)grow * DD + gcol;
                const float* rp1 = aux1 + (size_t)(grow + 8) * DD + gcol;
                v0 += rp0[0] + aux2[gcol];
                v1 += rp0[1] + aux2[gcol + 1];
                v2 += rp1[0] + aux2[gcol];
                v3 += rp1[1] + aux2[gcol + 1];
            }
            *(float2*)(C + (size_t)grow * DD + gcol)       = make_float2(v0, v1);
            *(float2*)(C + (size_t)(grow + 8) * DD + gcol) = make_float2(v2, v3);
        }
    }
}

// =================== transpose 1024x1024 + tf32 round ====================
__global__ void k_transpose(const float* __restrict__ src, float* __restrict__ dst) {
    __shared__ float t[32][33];
    int c0 = blockIdx.x * 32, r0 = blockIdx.y * 32;
    int x = threadIdx.x, y = threadIdx.y;
    #pragma unroll
    for (int j = 0; j < 32; j += 8)
        t[y + j][x] = src[(size_t)(r0 + y + j) * DD + c0 + x];
    __syncthreads();
    #pragma unroll
    for (int j = 0; j < 32; j += 8)
        dst[(size_t)(c0 + y + j) * DD + r0 + x] = to_tf32(t[x][y + j]);
}

// =================== tf32-rounded copy ===================================
__global__ void k_round(const float* __restrict__ src, float* __restrict__ dst,
                        int n4) {
    int i = blockIdx.x * 256 + threadIdx.x;
    if (i < n4) {
        float4 v = ((const float4*)src)[i];
        v.x = to_tf32(v.x); v.y = to_tf32(v.y);
        v.z = to_tf32(v.z); v.w = to_tf32(v.w);
        ((float4*)dst)[i] = v;
    }
}

// =================== vb = vector @ ff1_bot + b1 ==========================
__global__ void k_vb(const float* __restrict__ vec, const float* __restrict__ t1,
                     const float* __restrict__ bias, float* __restrict__ vb) {
    __shared__ float sv[DD];
    int b = blockIdx.y;
    for (int i = threadIdx.x; i < DD; i += 256) sv[i] = vec[(size_t)b * DD + i];
    __syncthreads();
    int d = blockIdx.x * 256 + threadIdx.x;
    const float4* tp = (const float4*)(t1 + (size_t)d * DD);
    const float4* vp = (const float4*)sv;
    float s = 0.f;
    #pragma unroll 4
    for (int i = 0; i < DD / 4; i++) {
        float4 a = tp[i], v = vp[i];
        s += a.x * v.x + a.y * v.y + a.z * v.z + a.w * v.w;
    }
    vb[(size_t)b * DD + d] = s + bias[d];
}

// =================== logits: warp-per-row, W^T in smem ===================
__global__ void k_logits(const float* __restrict__ inputs,
                         const float* __restrict__ W,
                         float* __restrict__ logits) {
    extern __shared__ float Wt[];   // [16][1024]
    int tid = threadIdx.x;
    for (int idx = tid; idx < DD * HH; idx += 256) {
        int i = idx >> 4, h = idx & 15;
        Wt[h * DD + i] = W[idx];
    }
    __syncthreads();
    int warp = tid >> 5, lane = tid & 31;
    for (int rr = 0; rr < 4; rr++) {
        int r = blockIdx.x * 32 + warp * 4 + rr;
        const float4* xp = (const float4*)(inputs + (size_t)r * DD);
        float acc[HH];
        #pragma unroll
        for (int h = 0; h < HH; h++) acc[h] = 0.f;
        #pragma unroll
        for (int j = 0; j < 8; j++) {
            float4 x = xp[lane + 32 * j];
            int i0 = (lane + 32 * j) * 4;
            #pragma unroll
            for (int h = 0; h < HH; h++) {
                float4 w = *(const float4*)&Wt[h * DD + i0];
                acc[h] += x.x * w.x + x.y * w.y + x.z * w.z + x.w * w.w;
            }
        }
        #pragma unroll
        for (int h = 0; h < HH; h++) {
            #pragma unroll
            for (int o = 16; o > 0; o >>= 1)
                acc[h] += __shfl_xor_sync(0xffffffffu, acc[h], o);
        }
        if (lane == 0) {
            #pragma unroll
            for (int h = 0; h < HH; h++) logits[(size_t)r * HH + h] = acc[h];
        }
    }
}

// ------------- per (b,h): max over S, then att = exp((x-max)*temp) -------
__global__ void k_att_norm(float* __restrict__ logits, const float* __restrict__ temp) {
    int b = blockIdx.x >> 4, h = blockIdx.x & 15;
    float* p = logits + (size_t)b * SS * HH + h;
    float m = -3.4e38f;
    for (int s = threadIdx.x; s < SS; s += 256) m = fmaxf(m, p[(size_t)s * HH]);
    __shared__ float red[256];
    red[threadIdx.x] = m; __syncthreads();
    for (int o = 128; o > 0; o >>= 1) {
        if (threadIdx.x < o) red[threadIdx.x] = fmaxf(red[threadIdx.x], red[threadIdx.x + o]);
        __syncthreads();
    }
    m = red[0];
    float t = temp[h];
    for (int s = threadIdx.x; s < SS; s += 256) {
        size_t idx = (size_t)s * HH;
        p[idx] = expf((p[idx] - m) * t);
    }
}

// ---------------- segmented scan over S (float4) ------------------------
#define DD4 (DD/4)
__global__ void k_scan1(const float4* __restrict__ V, float4* __restrict__ segsum) {
    int c = blockIdx.x * 128 + threadIdx.x;
    int seg = blockIdx.y, b = blockIdx.z;
    const float4* p = V + ((size_t)b * SS + (size_t)seg * SEG) * DD4 + c;
    float sx = 0.f, sy = 0.f, sz = 0.f, sw = 0.f;
    #pragma unroll 8
    for (int i = 0; i < SEG; i++) {
        float4 v = p[(size_t)i * DD4];
        sx += v.x; sy += v.y; sz += v.z; sw += v.w;
    }
    segsum[((size_t)b * NSEG + seg) * DD4 + c] = make_float4(sx, sy, sz, sw);
}

__global__ void k_scan2(float4* __restrict__ segsum) {
    int b = blockIdx.x, c = threadIdx.x;
    float4 run = make_float4(0.f, 0.f, 0.f, 0.f);
    for (int seg = 0; seg < NSEG; seg++) {
        size_t idx = ((size_t)b * NSEG + seg) * DD4 + c;
        float4 v = segsum[idx];
        segsum[idx] = run;
        run.x += v.x; run.y += v.y; run.z += v.z; run.w += v.w;
    }
}

__global__ void k_scan3(float4* __restrict__ V, const float4* __restrict__ segsum,
                        const float* __restrict__ att) {
    int c = blockIdx.x * 128 + threadIdx.x;
    int seg = blockIdx.y, b = blockIdx.z;
    int h = c >> 4;            // 16 float4 groups per head
    float4 run = segsum[((size_t)b * NSEG + seg) * DD4 + c];
    size_t base = (size_t)b * SS + (size_t)seg * SEG;
    float4* p = V + base * DD4 + c;
    const float* ap = att + base * HH + h;
    #pragma unroll 4
    for (int i = 0; i < SEG; i++) {
        float4 v = p[(size_t)i * DD4];
        run.x += v.x; run.y += v.y; run.z += v.z; run.w += v.w;
        float a = ap[(size_t)i * HH];
        float cnt = (float)(seg * SEG + i + 1);
        float s = a / (a * cnt + 1e-30f);
        p[(size_t)i * DD4] = make_float4(to_tf32(run.x * s), to_tf32(run.y * s),
                                         to_tf32(run.z * s), to_tf32(run.w * s));
    }
}

// ---------------- LayerNorm (in place over d_out rows) ------------------
__global__ void k_ln(float* __restrict__ X, const float* __restrict__ g,
                     const float* __restrict__ be) {
    int r = blockIdx.x;
    float* p = X + (size_t)r * DD;
    int i = threadIdx.x * 4;
    float4 x = *(const float4*)(p + i);
    __shared__ float red[256];
    float s = x.x + x.y + x.z + x.w;
    red[threadIdx.x] = s; __syncthreads();
    for (int o = 128; o > 0; o >>= 1) {
        if (threadIdx.x < o) red[threadIdx.x] += red[threadIdx.x + o];
        __syncthreads();
    }
    float mean = red[0] * (1.f / DD);
    __syncthreads();
    float d0 = x.x - mean, d1 = x.y - mean, d2 = x.z - mean, d3 = x.w - mean;
    red[threadIdx.x] = d0 * d0 + d1 * d1 + d2 * d2 + d3 * d3;
    __syncthreads();
    for (int o = 128; o > 0; o >>= 1) {
        if (threadIdx.x < o) red[threadIdx.x] += red[threadIdx.x + o];
        __syncthreads();
    }
    float inv = rsqrtf(red[0] * (1.f / DD) + 1e-6f);
    float4 o4;
    o4.x = d0 * inv * g[i + 0] + be[i + 0];
    o4.y = d1 * inv * g[i + 1] + be[i + 1];
    o4.z = d2 * inv * g[i + 2] + be[i + 2];
    o4.w = d3 * inv * g[i + 3] + be[i + 3];
    *(float4*)(p + i) = o4;
}

// ---------------- launcher ----------------------------------------------
extern "C" void kernel_launch(void* const* d_in, const int* in_sizes, int n_in,
                              void* d_out, int out_size) {
    (void)in_sizes; (void)n_in; (void)out_size;
    const float* inputs   = (const float*)d_in[0];
    const float* vector   = (const float*)d_in[1];
    const float* attw     = (const float*)d_in[2];
    const float* temp     = (const float*)d_in[3];
    const float* values   = (const float*)d_in[4];
    const float* oper     = (const float*)d_in[5];
    const float* ff1      = (const float*)d_in[6];
    const float* ff1_bias = (const float*)d_in[7];
    const float* ff2      = (const float*)d_in[8];
    const float* ff2_bias = (const float*)d_in[9];
    const float* ln_gamma = (const float*)d_in[10];
    const float* ln_beta  = (const float*)d_in[11];
    float* out = (float*)d_out;

    float *att_p, *v_p, *seg_p, *h1_p, *inr_p, *valT_p, *f1tT_p, *t1_p, *ff2T_p,
          *operr_p, *owT_p, *vb_p;
    cudaGetSymbolAddress((void**)&att_p,   g_att);
    cudaGetSymbolAddress((void**)&v_p,     g_v);
    cudaGetSymbolAddress((void**)&seg_p,   g_seg);
    cudaGetSymbolAddress((void**)&h1_p,    g_h1);
    cudaGetSymbolAddress((void**)&inr_p,   g_inr);
    cudaGetSymbolAddress((void**)&valT_p,  g_valT);
    cudaGetSymbolAddress((void**)&f1tT_p,  g_f1tT);
    cudaGetSymbolAddress((void**)&t1_p,    g_t1);
    cudaGetSymbolAddress((void**)&ff2T_p,  g_ff2T);
    cudaGetSymbolAddress((void**)&operr_p, g_operr);
    cudaGetSymbolAddress((void**)&owT_p,   g_owT);
    cudaGetSymbolAddress((void**)&vb_p,    g_vb);

    cudaFuncSetAttribute(gemm_mma<0>, cudaFuncAttributeMaxDynamicSharedMemorySize, GEMM_SMEM);
    cudaFuncSetAttribute(gemm_mma<1>, cudaFuncAttributeMaxDynamicSharedMemorySize, GEMM_SMEM);
    cudaFuncSetAttribute(gemm_mma<2>, cudaFuncAttributeMaxDynamicSharedMemorySize, GEMM_SMEM);
    cudaFuncSetAttribute(gemm_mma<3>, cudaFuncAttributeMaxDynamicSharedMemorySize, GEMM_SMEM);
    cudaFuncSetAttribute(k_logits, cudaFuncAttributeMaxDynamicSharedMemorySize, 65536);

    dim3 tb(32, 8), tg(32, 32);
    k_transpose<<<tg, tb>>>(values, valT_p);
    k_transpose<<<tg, tb>>>(ff1, f1tT_p);
    k_transpose<<<tg, tb>>>(ff1 + (size_t)DD * DD, t1_p);
    k_transpose<<<tg, tb>>>(ff2, ff2T_p);
    k_round<<<(DD * DD / 4 + 255) / 256, 256>>>(oper, operr_p, DD * DD / 4);
    k_round<<<((int)((size_t)MR * DD / 4) + 255) / 256, 256>>>(inputs, inr_p,
                                                               (int)((size_t)MR * DD / 4));

    k_vb<<<dim3(DD / 256, BB), 256>>>(vector, t1_p, ff1_bias, vb_p);

    // owT[n][f] = sum_dv t1[n][dv] * operator[f][dv]  (tf32 out)
    gemm_mma<1><<<dim3(8, 8), 256, GEMM_SMEM>>>(t1_p, operr_p, nullptr, nullptr,
                                                owT_p, nullptr, nullptr);

    k_logits<<<MR / 32, 256, 65536>>>(inputs, attw, att_p);
    k_att_norm<<<BB * HH, 256>>>(att_p, temp);

    // v = inputs @ values
    gemm_mma<0><<<dim3(8, MR / 128), 256, GEMM_SMEM>>>(inr_p, valT_p, nullptr, nullptr,
                                                       v_p, nullptr, nullptr);

    // causal cumsum + att scaling
    dim3 scanGrid(2, NSEG, BB);
    k_scan1<<<scanGrid, 128>>>((const float4*)v_p, (float4*)seg_p);
    k_scan2<<<BB, 256>>>((float4*)seg_p);
    k_scan3<<<scanGrid, 128>>>((float4*)v_p, (const float4*)seg_p, att_p);

    // h1 = relu(inputs@ff1_top + attn@OW + vb)
    gemm_mma<2><<<dim3(8, MR / 128), 256, GEMM_SMEM>>>(inr_p, f1tT_p, v_p, owT_p,
                                                       h1_p, nullptr, vb_p);

    // out = h1 @ ff2 + b2 + inputs
    gemm_mma<3><<<dim3(8, MR / 128), 256, GEMM_SMEM>>>(h1_p, ff2T_p, nullptr, nullptr,
                                                       out, inputs, ff2_bias);

    k_ln<<<MR, 256>>>(out, ln_gamma, ln_beta);
}

// round 9
// speedup vs baseline: 5.1199x; 1.4639x over previous
#include <cuda_runtime.h>
#include <cuda_fp16.h>
#include <math.h>
#include <stdint.h>

// Problem constants
#define BB   4
#define SS   4096
#define DD   1024
#define HH   16
#define MR   (BB*SS)          // 16384 rows
#define SEG  128
#define NSEG (SS/SEG)         // 32

#define NST  3                // pipeline stages
#define STB  32768            // bytes per stage (A 16KB + B 16KB)
#define GEMM_SMEM (NST*STB)   // 96 KB

// ---------------- scratch (static device globals) ------------------------
__device__ float  g_att[(size_t)BB*SS*HH];
__device__ float  g_v[(size_t)MR*DD];          // v (fp32, pre-scan)
__device__ float  g_seg[(size_t)BB*NSEG*DD];
__device__ float  g_vb [(size_t)BB*DD];
__device__ __half g_in_h[(size_t)MR*DD];       // inputs (half)
__device__ __half g_attn_h[(size_t)MR*DD];     // attn_out (half)
__device__ __half g_h1h[(size_t)MR*DD];        // ff1 hidden (half)
__device__ __half g_valTh[(size_t)DD*DD];
__device__ __half g_f1tTh[(size_t)DD*DD];
__device__ __half g_t1h [(size_t)DD*DD];
__device__ __half g_ff2Th[(size_t)DD*DD];
__device__ __half g_operh[(size_t)DD*DD];
__device__ __half g_owTh[(size_t)DD*DD];

// =================== helpers =============================================
__device__ __forceinline__ uint32_t smem_u32(const void* p) {
    uint32_t a;
    asm("{ .reg .u64 t; cvta.to.shared.u64 t, %1; cvt.u32.u64 %0, t; }"
        : "=r"(a) : "l"(p));
    return a;
}
__device__ __forceinline__ void cp16(uint32_t s, const void* g) {
    asm volatile("cp.async.cg.shared.global [%0], [%1], 16;"
                 :: "r"(s), "l"(g) : "memory");
}
__device__ __forceinline__ void cp_commit() {
    asm volatile("cp.async.commit_group;" ::: "memory");
}
template<int N>
__device__ __forceinline__ void cp_wait() {
    asm volatile("cp.async.wait_group %0;" :: "n"(N) : "memory");
}
__device__ __forceinline__ void ldm_x4(uint32_t* r, uint32_t addr) {
    asm volatile("ldmatrix.sync.aligned.m8n8.x4.shared.b16 {%0,%1,%2,%3}, [%4];"
                 : "=r"(r[0]), "=r"(r[1]), "=r"(r[2]), "=r"(r[3]) : "r"(addr));
}
__device__ __forceinline__ void mma16(float* d, const uint32_t* a, const uint32_t* b) {
    asm volatile(
        "mma.sync.aligned.m16n8k16.row.col.f32.f16.f16.f32 "
        "{%0,%1,%2,%3}, {%4,%5,%6,%7}, {%8,%9}, {%0,%1,%2,%3};"
        : "+f"(d[0]), "+f"(d[1]), "+f"(d[2]), "+f"(d[3])
        : "r"(a[0]), "r"(a[1]), "r"(a[2]), "r"(a[3]), "r"(b[0]), "r"(b[1]));
}
__device__ __forceinline__ uint32_t pack_h2(float a, float b) {
    __half2 h = __floats2half2_rn(a, b);
    return *reinterpret_cast<uint32_t*>(&h);
}

// =================== fp16 mma.sync GEMM (ldmatrix + 3-stage) =============
// C[m,n] = sum_k A1[m,k]*B1[n,k] (+ A2[m,k]*B2[n,k] if A2), K=1024 per pair.
// MODE 0: fp32 out              MODE 1: half out
// MODE 2: half(relu(acc + aux2[(row>>12)*DD+col]))
// MODE 3: fp32: acc + aux1[row*DD+col] + aux2[col]
template<int MODE>
__global__ void __launch_bounds__(256, 2)
gemm_mma(const __half* __restrict__ A1, const __half* __restrict__ B1,
         const __half* __restrict__ A2, const __half* __restrict__ B2,
         void* __restrict__ Cv,
         const float* __restrict__ aux1, const float* __restrict__ aux2) {
    extern __shared__ char sm[];
    const uint32_t sbase = smem_u32(sm);
    const int tid = threadIdx.x, lane = tid & 31, wid = tid >> 5;
    const int wm = (wid & 3) * 32, wn = (wid >> 2) * 64;
    const int m0 = blockIdx.y * 128, n0 = blockIdx.x * 128;
    const int r4 = lane >> 2, l4 = lane & 3;
    const int nch = A2 ? 32 : 16;   // chunks of K=64 halves

    // cp.async mapping: row = tid>>1, 4 x 16B chunks at (tid&1)*4
    const int lrow = tid >> 1;
    const int lc0  = (tid & 1) * 4;
    const int lr7  = lrow & 7;

    // ldmatrix per-lane row/parity (identical mapping to verified tf32 path)
    const int a_row = wm + (lane & 15);
    const int a_hb  = lane >> 4;
    const int b_rlo = (lane & 7) + ((lane >> 4) & 1) * 8;
    const int b_hb  = (lane >> 3) & 1;

    float acc[2][8][4];
    #pragma unroll
    for (int i = 0; i < 2; i++)
        #pragma unroll
        for (int j = 0; j < 8; j++)
            #pragma unroll
            for (int q = 0; q < 4; q++) acc[i][j][q] = 0.f;

    auto load_chunk = [&](int c) {
        const __half* Ap = (c < 16) ? A1 : A2;
        const __half* Bp = (c < 16) ? B1 : B2;
        const int k0 = (c & 15) * 64;          // halves
        const uint32_t st = sbase + (uint32_t)((c % NST) * STB);
        const __half* ga = Ap + (size_t)(m0 + lrow) * DD + k0 + lc0 * 8;
        const __half* gb = Bp + (size_t)(n0 + lrow) * DD + k0 + lc0 * 8;
        const uint32_t rowoff = (uint32_t)lrow * 128u;
        #pragma unroll
        for (int q = 0; q < 4; q++) {
            uint32_t sc = (uint32_t)(((lc0 + q) ^ lr7) << 4);
            cp16(st + rowoff + sc,           ga + q * 8);
            cp16(st + 16384u + rowoff + sc,  gb + q * 8);
        }
        cp_commit();
    };

    load_chunk(0);
    load_chunk(1);

    for (int c = 0; c < nch; c++) {
        if (c + 1 < nch) cp_wait<1>(); else cp_wait<0>();
        __syncthreads();

        const uint32_t Ab = sbase + (uint32_t)((c % NST) * STB);
        const uint32_t Bb = Ab + 16384u;
        #pragma unroll
        for (int ks = 0; ks < 4; ks++) {     // k16 steps within K=64 chunk
            uint32_t a[2][4], bg[4][4];
            #pragma unroll
            for (int i = 0; i < 2; i++) {
                int row = a_row + i * 16;
                int ch = 2 * ks + a_hb;
                ldm_x4(a[i], Ab + row * 128 + ((ch ^ (row & 7)) << 4));
            }
            #pragma unroll
            for (int g = 0; g < 4; g++) {
                int row = wn + g * 16 + b_rlo;
                int ch = 2 * ks + b_hb;
                ldm_x4(bg[g], Bb + row * 128 + ((ch ^ (row & 7)) << 4));
            }
            #pragma unroll
            for (int i = 0; i < 2; i++)
                #pragma unroll
                for (int j = 0; j < 8; j++)
                    mma16(acc[i][j], a[i], &bg[j >> 1][(j & 1) * 2]);
        }
        __syncthreads();
        if (c + 2 < nch) load_chunk(c + 2);
    }

    // epilogue
    float* Cf = (float*)Cv;
    __half* Ch = (__half*)Cv;
    #pragma unroll
    for (int i = 0; i < 2; i++) {
        int grow = m0 + wm + i * 16 + r4;
        #pragma unroll
        for (int j = 0; j < 8; j++) {
            int gcol = n0 + wn + j * 8 + l4 * 2;
            float v0 = acc[i][j][0], v1 = acc[i][j][1];
            float v2 = acc[i][j][2], v3 = acc[i][j][3];
            if (MODE == 0) {
                *(float2*)(Cf + (size_t)grow * DD + gcol)       = make_float2(v0, v1);
                *(float2*)(Cf + (size_t)(grow + 8) * DD + gcol) = make_float2(v2, v3);
            }
            if (MODE == 1) {
                *(uint32_t*)(Ch + (size_t)grow * DD + gcol)       = pack_h2(v0, v1);
                *(uint32_t*)(Ch + (size_t)(grow + 8) * DD + gcol) = pack_h2(v2, v3);
            }
            if (MODE == 2) {
                const float* vb0 = aux2 + (size_t)(grow >> 12) * DD + gcol;
                v0 = fmaxf(v0 + vb0[0], 0.f);
                v1 = fmaxf(v1 + vb0[1], 0.f);
                v2 = fmaxf(v2 + vb0[0], 0.f);
                v3 = fmaxf(v3 + vb0[1], 0.f);
                *(uint32_t*)(Ch + (size_t)grow * DD + gcol)       = pack_h2(v0, v1);
                *(uint32_t*)(Ch + (size_t)(grow + 8) * DD + gcol) = pack_h2(v2, v3);
            }
            if (MODE == 3) {
                const float* rp0 = aux1 + (size_t)grow * DD + gcol;
                const float* rp1 = aux1 + (size_t)(grow + 8) * DD + gcol;
                v0 += rp0[0] + aux2[gcol];
                v1 += rp0[1] + aux2[gcol + 1];
                v2 += rp1[0] + aux2[gcol];
                v3 += rp1[1] + aux2[gcol + 1];
                *(float2*)(Cf + (size_t)grow * DD + gcol)       = make_float2(v0, v1);
                *(float2*)(Cf + (size_t)(grow + 8) * DD + gcol) = make_float2(v2, v3);
            }
        }
    }
}

// =================== transpose 1024x1024 fp32 -> half ====================
__global__ void k_transpose_h(const float* __restrict__ src, __half* __restrict__ dst) {
    __shared__ float t[32][33];
    int c0 = blockIdx.x * 32, r0 = blockIdx.y * 32;
    int x = threadIdx.x, y = threadIdx.y;
    #pragma unroll
    for (int j = 0; j < 32; j += 8)
        t[y + j][x] = src[(size_t)(r0 + y + j) * DD + c0 + x];
    __syncthreads();
    #pragma unroll
    for (int j = 0; j < 32; j += 8)
        dst[(size_t)(c0 + y + j) * DD + r0 + x] = __float2half_rn(t[x][y + j]);
}

// =================== fp32 -> half copy ===================================
__global__ void k_cvt_h(const float* __restrict__ src, __half* __restrict__ dst,
                        int n4) {
    int i = blockIdx.x * 256 + threadIdx.x;
    if (i < n4) {
        float4 v = ((const float4*)src)[i];
        ((uint2*)dst)[i] = make_uint2(pack_h2(v.x, v.y), pack_h2(v.z, v.w));
    }
}

// =================== vb = vector @ ff1_bot + b1 (half t1) ================
__global__ void k_vb(const float* __restrict__ vec, const __half* __restrict__ t1,
                     const float* __restrict__ bias, float* __restrict__ vb) {
    __shared__ float sv[DD];
    int b = blockIdx.y;
    for (int i = threadIdx.x; i < DD; i += 256) sv[i] = vec[(size_t)b * DD + i];
    __syncthreads();
    int d = blockIdx.x * 256 + threadIdx.x;
    const __half2* tp = (const __half2*)(t1 + (size_t)d * DD);
    float s = 0.f;
    #pragma unroll 4
    for (int i = 0; i < DD / 2; i++) {
        float2 a = __half22float2(tp[i]);
        s += a.x * sv[2 * i] + a.y * sv[2 * i + 1];
    }
    vb[(size_t)b * DD + d] = s + bias[d];
}

// =================== logits: warp-per-row, W^T in smem ===================
__global__ void k_logits(const float* __restrict__ inputs,
                         const float* __restrict__ W,
                         float* __restrict__ logits) {
    extern __shared__ float Wt[];   // [16][1024]
    int tid = threadIdx.x;
    for (int idx = tid; idx < DD * HH; idx += 256) {
        int i = idx >> 4, h = idx & 15;
        Wt[h * DD + i] = W[idx];
    }
    __syncthreads();
    int warp = tid >> 5, lane = tid & 31;
    for (int rr = 0; rr < 4; rr++) {
        int r = blockIdx.x * 32 + warp * 4 + rr;
        const float4* xp = (const float4*)(inputs + (size_t)r * DD);
        float acc[HH];
        #pragma unroll
        for (int h = 0; h < HH; h++) acc[h] = 0.f;
        #pragma unroll
        for (int j = 0; j < 8; j++) {
            float4 x = xp[lane + 32 * j];
            int i0 = (lane + 32 * j) * 4;
            #pragma unroll
            for (int h = 0; h < HH; h++) {
                float4 w = *(const float4*)&Wt[h * DD + i0];
                acc[h] += x.x * w.x + x.y * w.y + x.z * w.z + x.w * w.w;
            }
        }
        #pragma unroll
        for (int h = 0; h < HH; h++) {
            #pragma unroll
            for (int o = 16; o > 0; o >>= 1)
                acc[h] += __shfl_xor_sync(0xffffffffu, acc[h], o);
        }
        if (lane == 0) {
            #pragma unroll
            for (int h = 0; h < HH; h++) logits[(size_t)r * HH + h] = acc[h];
        }
    }
}

// ------------- per (b,h): max over S, then att = exp((x-max)*temp) -------
__global__ void k_att_norm(float* __restrict__ logits, const float* __restrict__ temp) {
    int b = blockIdx.x >> 4, h = blockIdx.x & 15;
    float* p = logits + (size_t)b * SS * HH + h;
    float m = -3.4e38f;
    for (int s = threadIdx.x; s < SS; s += 256) m = fmaxf(m, p[(size_t)s * HH]);
    __shared__ float red[256];
    red[threadIdx.x] = m; __syncthreads();
    for (int o = 128; o > 0; o >>= 1) {
        if (threadIdx.x < o) red[threadIdx.x] = fmaxf(red[threadIdx.x], red[threadIdx.x + o]);
        __syncthreads();
    }
    m = red[0];
    float t = temp[h];
    for (int s = threadIdx.x; s < SS; s += 256) {
        size_t idx = (size_t)s * HH;
        p[idx] = expf((p[idx] - m) * t);
    }
}

// ---------------- segmented scan over S (float4) ------------------------
#define DD4 (DD/4)
__global__ void k_scan1(const float4* __restrict__ V, float4* __restrict__ segsum) {
    int c = blockIdx.x * 128 + threadIdx.x;
    int seg = blockIdx.y, b = blockIdx.z;
    const float4* p = V + ((size_t)b * SS + (size_t)seg * SEG) * DD4 + c;
    float sx = 0.f, sy = 0.f, sz = 0.f, sw = 0.f;
    #pragma unroll 8
    for (int i = 0; i < SEG; i++) {
        float4 v = p[(size_t)i * DD4];
        sx += v.x; sy += v.y; sz += v.z; sw += v.w;
    }
    segsum[((size_t)b * NSEG + seg) * DD4 + c] = make_float4(sx, sy, sz, sw);
}

__global__ void k_scan2(float4* __restrict__ segsum) {
    int b = blockIdx.x, c = threadIdx.x;
    float4 run = make_float4(0.f, 0.f, 0.f, 0.f);
    for (int seg = 0; seg < NSEG; seg++) {
        size_t idx = ((size_t)b * NSEG + seg) * DD4 + c;
        float4 v = segsum[idx];
        segsum[idx] = run;
        run.x += v.x; run.y += v.y; run.z += v.z; run.w += v.w;
    }
}

// prefix + att scaling; writes attn_out as half
__global__ void k_scan3(const float4* __restrict__ V, const float4* __restrict__ segsum,
                        const float* __restrict__ att, __half* __restrict__ out) {
    int c = blockIdx.x * 128 + threadIdx.x;
    int seg = blockIdx.y, b = blockIdx.z;
    int h = c >> 4;            // 16 float4 groups per head
    float4 run = segsum[((size_t)b * NSEG + seg) * DD4 + c];
    size_t base = (size_t)b * SS + (size_t)seg * SEG;
    const float4* p = V + base * DD4 + c;
    const float* ap = att + base * HH + h;
    __half* op = out + base * DD + c * 4;
    #pragma unroll 4
    for (int i = 0; i < SEG; i++) {
        float4 v = p[(size_t)i * DD4];
        run.x += v.x; run.y += v.y; run.z += v.z; run.w += v.w;
        float a = ap[(size_t)i * HH];
        float cnt = (float)(seg * SEG + i + 1);
        float s = a / (a * cnt + 1e-30f);
        *(uint32_t*)(op + (size_t)i * DD)     = pack_h2(run.x * s, run.y * s);
        *(uint32_t*)(op + (size_t)i * DD + 2) = pack_h2(run.z * s, run.w * s);
    }
}

// ---------------- LayerNorm (in place over d_out rows) ------------------
__global__ void k_ln(float* __restrict__ X, const float* __restrict__ g,
                     const float* __restrict__ be) {
    int r = blockIdx.x;
    float* p = X + (size_t)r * DD;
    int i = threadIdx.x * 4;
    float4 x = *(const float4*)(p + i);
    __shared__ float red[256];
    float s = x.x + x.y + x.z + x.w;
    red[threadIdx.x] = s; __syncthreads();
    for (int o = 128; o > 0; o >>= 1) {
        if (threadIdx.x < o) red[threadIdx.x] += red[threadIdx.x + o];
        __syncthreads();
    }
    float mean = red[0] * (1.f / DD);
    __syncthreads();
    float d0 = x.x - mean, d1 = x.y - mean, d2 = x.z - mean, d3 = x.w - mean;
    red[threadIdx.x] = d0 * d0 + d1 * d1 + d2 * d2 + d3 * d3;
    __syncthreads();
    for (int o = 128; o > 0; o >>= 1) {
        if (threadIdx.x < o) red[threadIdx.x] += red[threadIdx.x + o];
        __syncthreads();
    }
    float inv = rsqrtf(red[0] * (1.f / DD) + 1e-6f);
    float4 o4;
    o4.x = d0 * inv * g[i + 0] + be[i + 0];
    o4.y = d1 * inv * g[i + 1] + be[i + 1];
    o4.z = d2 * inv * g[i + 2] + be[i + 2];
    o4.w = d3 * inv * g[i + 3] + be[i + 3];
    *(float4*)(p + i) = o4;
}

// ---------------- launcher ----------------------------------------------
extern "C" void kernel_launch(void* const* d_in, const int* in_sizes, int n_in,
                              void* d_out, int out_size) {
    (void)in_sizes; (void)n_in; (void)out_size;
    const float* inputs   = (const float*)d_in[0];
    const float* vector   = (const float*)d_in[1];
    const float* attw     = (const float*)d_in[2];
    const float* temp     = (const float*)d_in[3];
    const float* values   = (const float*)d_in[4];
    const float* oper     = (const float*)d_in[5];
    const float* ff1      = (const float*)d_in[6];
    const float* ff1_bias = (const float*)d_in[7];
    const float* ff2      = (const float*)d_in[8];
    const float* ff2_bias = (const float*)d_in[9];
    const float* ln_gamma = (const float*)d_in[10];
    const float* ln_beta  = (const float*)d_in[11];
    float* out = (float*)d_out;

    float *att_p, *v_p, *seg_p, *vb_p;
    __half *inh_p, *attnh_p, *h1h_p, *valT_p, *f1tT_p, *t1_p, *ff2T_p, *operh_p, *owT_p;
    cudaGetSymbolAddress((void**)&att_p,   g_att);
    cudaGetSymbolAddress((void**)&v_p,     g_v);
    cudaGetSymbolAddress((void**)&seg_p,   g_seg);
    cudaGetSymbolAddress((void**)&vb_p,    g_vb);
    cudaGetSymbolAddress((void**)&inh_p,   g_in_h);
    cudaGetSymbolAddress((void**)&attnh_p, g_attn_h);
    cudaGetSymbolAddress((void**)&h1h_p,   g_h1h);
    cudaGetSymbolAddress((void**)&valT_p,  g_valTh);
    cudaGetSymbolAddress((void**)&f1tT_p,  g_f1tTh);
    cudaGetSymbolAddress((void**)&t1_p,    g_t1h);
    cudaGetSymbolAddress((void**)&ff2T_p,  g_ff2Th);
    cudaGetSymbolAddress((void**)&operh_p, g_operh);
    cudaGetSymbolAddress((void**)&owT_p,   g_owTh);

    cudaFuncSetAttribute(gemm_mma<0>, cudaFuncAttributeMaxDynamicSharedMemorySize, GEMM_SMEM);
    cudaFuncSetAttribute(gemm_mma<1>, cudaFuncAttributeMaxDynamicSharedMemorySize, GEMM_SMEM);
    cudaFuncSetAttribute(gemm_mma<2>, cudaFuncAttributeMaxDynamicSharedMemorySize, GEMM_SMEM);
    cudaFuncSetAttribute(gemm_mma<3>, cudaFuncAttributeMaxDynamicSharedMemorySize, GEMM_SMEM);
    cudaFuncSetAttribute(k_logits, cudaFuncAttributeMaxDynamicSharedMemorySize, 65536);

    dim3 tb(32, 8), tg(32, 32);
    k_transpose_h<<<tg, tb>>>(values, valT_p);
    k_transpose_h<<<tg, tb>>>(ff1, f1tT_p);
    k_transpose_h<<<tg, tb>>>(ff1 + (size_t)DD * DD, t1_p);
    k_transpose_h<<<tg, tb>>>(ff2, ff2T_p);
    k_cvt_h<<<(DD * DD / 4 + 255) / 256, 256>>>(oper, operh_p, DD * DD / 4);
    k_cvt_h<<<((int)((size_t)MR * DD / 4) + 255) / 256, 256>>>(inputs, inh_p,
                                                               (int)((size_t)MR * DD / 4));

    k_vb<<<dim3(DD / 256, BB), 256>>>(vector, t1_p, ff1_bias, vb_p);

    // owT[n][f] = sum_dv t1[n][dv] * operator[f][dv]  (half out)
    gemm_mma<1><<<dim3(8, 8), 256, GEMM_SMEM>>>(t1_p, operh_p, nullptr, nullptr,
                                                owT_p, nullptr, nullptr);

    k_logits<<<MR / 32, 256, 65536>>>(inputs, attw, att_p);
    k_att_norm<<<BB * HH, 256>>>(att_p, temp);

    // v = inputs @ values (fp32 out)
    gemm_mma<0><<<dim3(8, MR / 128), 256, GEMM_SMEM>>>(inh_p, valT_p, nullptr, nullptr,
                                                       v_p, nullptr, nullptr);

    // causal cumsum + att scaling -> half attn_out
    dim3 scanGrid(2, NSEG, BB);
    k_scan1<<<scanGrid, 128>>>((const float4*)v_p, (float4*)seg_p);
    k_scan2<<<BB, 256>>>((float4*)seg_p);
    k_scan3<<<scanGrid, 128>>>((const float4*)v_p, (const float4*)seg_p, att_p, attnh_p);

    // h1 = relu(inputs@ff1_top + attn@OW + vb)  (half out)
    gemm_mma<2><<<dim3(8, MR / 128), 256, GEMM_SMEM>>>(inh_p, f1tT_p, attnh_p, owT_p,
                                                       h1h_p, nullptr, vb_p);

    // out = h1 @ ff2 + b2 + inputs (fp32)
    gemm_mma<3><<<dim3(8, MR / 128), 256, GEMM_SMEM>>>(h1h_p, ff2T_p, nullptr, nullptr,
                                                       out, inputs, ff2_bias);

    k_ln<<<MR, 256>>>(out, ln_gamma, ln_beta);
}

// round 11
// speedup vs baseline: 5.2053x; 1.0167x over previous
#include <cuda_runtime.h>
#include <cuda_fp16.h>
#include <math.h>
#include <stdint.h>

// Problem constants
#define BB   4
#define SS   4096
#define DD   1024
#define HH   16
#define MR   (BB*SS)          // 16384 rows
#define SEG  128
#define NSEG (SS/SEG)         // 32

#define NST  3                // pipeline stages
#define STB  32768            // bytes per stage (A 16KB + B 16KB)
#define GEMM_SMEM (NST*STB)   // 96 KB

// ---------------- scratch (static device globals) ------------------------
__device__ float  g_att[(size_t)BB*SS*HH];
__device__ float  g_v[(size_t)MR*DD];          // v (fp32, pre-scan)
__device__ float  g_seg[(size_t)BB*NSEG*DD];
__device__ float  g_vb [(size_t)BB*DD];
__device__ __half g_in_h[(size_t)MR*DD];       // inputs (half)
__device__ __half g_attn_h[(size_t)MR*DD];     // attn_out (half)
__device__ __half g_h1h[(size_t)MR*DD];        // ff1 hidden (half)
__device__ __half g_valTh[(size_t)DD*DD];
__device__ __half g_f1tTh[(size_t)DD*DD];
__device__ __half g_t1h [(size_t)DD*DD];
__device__ __half g_ff2Th[(size_t)DD*DD];
__device__ __half g_operh[(size_t)DD*DD];
__device__ __half g_owTh[(size_t)DD*DD];

// =================== helpers =============================================
__device__ __forceinline__ uint32_t smem_u32(const void* p) {
    uint32_t a;
    asm("{ .reg .u64 t; cvta.to.shared.u64 t, %1; cvt.u32.u64 %0, t; }"
        : "=r"(a) : "l"(p));
    return a;
}
__device__ __forceinline__ void cp16(uint32_t s, const void* g) {
    asm volatile("cp.async.cg.shared.global [%0], [%1], 16;"
                 :: "r"(s), "l"(g) : "memory");
}
__device__ __forceinline__ void cp_commit() {
    asm volatile("cp.async.commit_group;" ::: "memory");
}
template<int N>
__device__ __forceinline__ void cp_wait() {
    asm volatile("cp.async.wait_group %0;" :: "n"(N) : "memory");
}
__device__ __forceinline__ void ldm_x4(uint32_t* r, uint32_t addr) {
    asm volatile("ldmatrix.sync.aligned.m8n8.x4.shared.b16 {%0,%1,%2,%3}, [%4];"
                 : "=r"(r[0]), "=r"(r[1]), "=r"(r[2]), "=r"(r[3]) : "r"(addr));
}
__device__ __forceinline__ void mma16(float* d, const uint32_t* a, const uint32_t* b) {
    asm volatile(
        "mma.sync.aligned.m16n8k16.row.col.f32.f16.f16.f32 "
        "{%0,%1,%2,%3}, {%4,%5,%6,%7}, {%8,%9}, {%0,%1,%2,%3};"
        : "+f"(d[0]), "+f"(d[1]), "+f"(d[2]), "+f"(d[3])
        : "r"(a[0]), "r"(a[1]), "r"(a[2]), "r"(a[3]), "r"(b[0]), "r"(b[1]));
}
__device__ __forceinline__ uint32_t pack_h2(float a, float b) {
    __half2 h = __floats2half2_rn(a, b);
    return *reinterpret_cast<uint32_t*>(&h);
}

// =================== fp16 mma.sync GEMM (ldmatrix + 3-stage) =============
// C[m,n] = sum_k A1[m,k]*B1[n,k] (+ A2[m,k]*B2[n,k] if A2), K=1024 per pair.
// MODE 0: fp32 out              MODE 1: half out
// MODE 2: half(relu(acc + aux2[(row>>12)*DD+col]))
// MODE 3: fp32: acc + aux1[row*DD+col] + aux2[col]
// MODE 4: fp32 out + per-tile column sums -> aux1 (segsum; tile == segment)
template<int MODE>
__global__ void __launch_bounds__(256, 2)
gemm_mma(const __half* __restrict__ A1, const __half* __restrict__ B1,
         const __half* __restrict__ A2, const __half* __restrict__ B2,
         void* __restrict__ Cv,
         float* __restrict__ aux1, const float* __restrict__ aux2) {
    extern __shared__ char sm[];
    const uint32_t sbase = smem_u32(sm);
    const int tid = threadIdx.x, lane = tid & 31, wid = tid >> 5;
    const int wm = (wid & 3) * 32, wn = (wid >> 2) * 64;
    const int m0 = blockIdx.y * 128, n0 = blockIdx.x * 128;
    const int r4 = lane >> 2, l4 = lane & 3;
    const int nch = A2 ? 32 : 16;   // chunks of K=64 halves

    // cp.async mapping: row = tid>>1, 4 x 16B chunks at (tid&1)*4
    const int lrow = tid >> 1;
    const int lc0  = (tid & 1) * 4;
    const int lr7  = lrow & 7;

    // ldmatrix per-lane row/parity
    const int a_row = wm + (lane & 15);
    const int a_hb  = lane >> 4;
    const int b_rlo = (lane & 7) + ((lane >> 4) & 1) * 8;
    const int b_hb  = (lane >> 3) & 1;

    float acc[2][8][4];
    #pragma unroll
    for (int i = 0; i < 2; i++)
        #pragma unroll
        for (int j = 0; j < 8; j++)
            #pragma unroll
            for (int q = 0; q < 4; q++) acc[i][j][q] = 0.f;

    auto load_chunk = [&](int c) {
        const __half* Ap = (c < 16) ? A1 : A2;
        const __half* Bp = (c < 16) ? B1 : B2;
        const int k0 = (c & 15) * 64;          // halves
        const uint32_t st = sbase + (uint32_t)((c % NST) * STB);
        const __half* ga = Ap + (size_t)(m0 + lrow) * DD + k0 + lc0 * 8;
        const __half* gb = Bp + (size_t)(n0 + lrow) * DD + k0 + lc0 * 8;
        const uint32_t rowoff = (uint32_t)lrow * 128u;
        #pragma unroll
        for (int q = 0; q < 4; q++) {
            uint32_t sc = (uint32_t)(((lc0 + q) ^ lr7) << 4);
            cp16(st + rowoff + sc,           ga + q * 8);
            cp16(st + 16384u + rowoff + sc,  gb + q * 8);
        }
        cp_commit();
    };

    load_chunk(0);
    load_chunk(1);

    for (int c = 0; c < nch; c++) {
        if (c + 1 < nch) cp_wait<1>(); else cp_wait<0>();
        __syncthreads();
        if (c + 2 < nch) load_chunk(c + 2);   // overlap load issue with compute

        const uint32_t Ab = sbase + (uint32_t)((c % NST) * STB);
        const uint32_t Bb = Ab + 16384u;
        #pragma unroll
        for (int ks = 0; ks < 4; ks++) {     // k16 steps within K=64 chunk
            uint32_t a[2][4], bg[4][4];
            #pragma unroll
            for (int i = 0; i < 2; i++) {
                int row = a_row + i * 16;
                int ch = 2 * ks + a_hb;
                ldm_x4(a[i], Ab + row * 128 + ((ch ^ (row & 7)) << 4));
            }
            #pragma unroll
            for (int g = 0; g < 4; g++) {
                int row = wn + g * 16 + b_rlo;
                int ch = 2 * ks + b_hb;
                ldm_x4(bg[g], Bb + row * 128 + ((ch ^ (row & 7)) << 4));
            }
            #pragma unroll
            for (int i = 0; i < 2; i++)
                #pragma unroll
                for (int j = 0; j < 8; j++)
                    mma16(acc[i][j], a[i], &bg[j >> 1][(j & 1) * 2]);
        }
        // no trailing barrier: next iteration's barrier orders compute vs the
        // load that overwrites this stage (3-stage ring, offset +2 == -1).
    }

    // epilogue
    float* Cf = (float*)Cv;
    __half* Ch = (__half*)Cv;
    float colsum[8][2];
    if (MODE == 4) {
        #pragma unroll
        for (int j = 0; j < 8; j++) { colsum[j][0] = 0.f; colsum[j][1] = 0.f; }
    }
    #pragma unroll
    for (int i = 0; i < 2; i++) {
        int grow = m0 + wm + i * 16 + r4;
        #pragma unroll
        for (int j = 0; j < 8; j++) {
            int gcol = n0 + wn + j * 8 + l4 * 2;
            float v0 = acc[i][j][0], v1 = acc[i][j][1];
            float v2 = acc[i][j][2], v3 = acc[i][j][3];
            if (MODE == 0 || MODE == 4) {
                *(float2*)(Cf + (size_t)grow * DD + gcol)       = make_float2(v0, v1);
                *(float2*)(Cf + (size_t)(grow + 8) * DD + gcol) = make_float2(v2, v3);
                if (MODE == 4) {
                    colsum[j][0] += v0 + v2;
                    colsum[j][1] += v1 + v3;
                }
            }
            if (MODE == 1) {
                *(uint32_t*)(Ch + (size_t)grow * DD + gcol)       = pack_h2(v0, v1);
                *(uint32_t*)(Ch + (size_t)(grow + 8) * DD + gcol) = pack_h2(v2, v3);
            }
            if (MODE == 2) {
                const float* vb0 = aux2 + (size_t)(grow >> 12) * DD + gcol;
                v0 = fmaxf(v0 + vb0[0], 0.f);
                v1 = fmaxf(v1 + vb0[1], 0.f);
                v2 = fmaxf(v2 + vb0[0], 0.f);
                v3 = fmaxf(v3 + vb0[1], 0.f);
                *(uint32_t*)(Ch + (size_t)grow * DD + gcol)       = pack_h2(v0, v1);
                *(uint32_t*)(Ch + (size_t)(grow + 8) * DD + gcol) = pack_h2(v2, v3);
            }
            if (MODE == 3) {
                const float* rp0 = aux1 + (size_t)grow * DD + gcol;
                const float* rp1 = aux1 + (size_t)(grow + 8) * DD + gcol;
                v0 += rp0[0] + aux2[gcol];
                v1 += rp0[1] + aux2[gcol + 1];
                v2 += rp1[0] + aux2[gcol];
                v3 += rp1[1] + aux2[gcol + 1];
                *(float2*)(Cf + (size_t)grow * DD + gcol)       = make_float2(v0, v1);
                *(float2*)(Cf + (size_t)(grow + 8) * DD + gcol) = make_float2(v2, v3);
            }
        }
    }

    if (MODE == 4) {
        // reduce over r4 (lane bits 2..4) -> every lane holds sum for its l4
        #pragma unroll
        for (int j = 0; j < 8; j++) {
            #pragma unroll
            for (int q = 0; q < 2; q++) {
                float s = colsum[j][q];
                s += __shfl_xor_sync(0xffffffffu, s, 4);
                s += __shfl_xor_sync(0xffffffffu, s, 8);
                s += __shfl_xor_sync(0xffffffffu, s, 16);
                colsum[j][q] = s;
            }
        }
        float* red = (float*)sm;     // [4][128]
        __syncthreads();             // mainloop smem no longer in use
        if (lane < 4) {
            #pragma unroll
            for (int j = 0; j < 8; j++) {
                red[(wid & 3) * 128 + wn + j * 8 + lane * 2 + 0] = colsum[j][0];
                red[(wid & 3) * 128 + wn + j * 8 + lane * 2 + 1] = colsum[j][1];
            }
        }
        __syncthreads();
        if (tid < 128) {
            float s = red[tid] + red[128 + tid] + red[256 + tid] + red[384 + tid];
            int b = m0 >> 12, seg = (m0 >> 7) & (NSEG - 1);
            aux1[((size_t)b * NSEG + seg) * DD + n0 + tid] = s;
        }
    }
}

// =================== transpose 1024x1024 fp32 -> half ====================
__global__ void k_transpose_h(const float* __restrict__ src, __half* __restrict__ dst) {
    __shared__ float t[32][33];
    int c0 = blockIdx.x * 32, r0 = blockIdx.y * 32;
    int x = threadIdx.x, y = threadIdx.y;
    #pragma unroll
    for (int j = 0; j < 32; j += 8)
        t[y + j][x] = src[(size_t)(r0 + y + j) * DD + c0 + x];
    __syncthreads();
    #pragma unroll
    for (int j = 0; j < 32; j += 8)
        dst[(size_t)(c0 + y + j) * DD + r0 + x] = __float2half_rn(t[x][y + j]);
}

// =================== fp32 -> half copy ===================================
__global__ void k_cvt_h(const float* __restrict__ src, __half* __restrict__ dst,
                        int n4) {
    int i = blockIdx.x * 256 + threadIdx.x;
    if (i < n4) {
        float4 v = ((const float4*)src)[i];
        ((uint2*)dst)[i] = make_uint2(pack_h2(v.x, v.y), pack_h2(v.z, v.w));
    }
}

// =================== vb = vector @ ff1_bot + b1 (half t1) ================
__global__ void k_vb(const float* __restrict__ vec, const __half* __restrict__ t1,
                     const float* __restrict__ bias, float* __restrict__ vb) {
    __shared__ float sv[DD];
    int b = blockIdx.y;
    for (int i = threadIdx.x; i < DD; i += 256) sv[i] = vec[(size_t)b * DD + i];
    __syncthreads();
    int d = blockIdx.x * 256 + threadIdx.x;
    const __half2* tp = (const __half2*)(t1 + (size_t)d * DD);
    float s = 0.f;
    #pragma unroll 4
    for (int i = 0; i < DD / 2; i++) {
        float2 a = __half22float2(tp[i]);
        s += a.x * sv[2 * i] + a.y * sv[2 * i + 1];
    }
    vb[(size_t)b * DD + d] = s + bias[d];
}

// ===== logits: warp-per-row, W^T in smem; also emits half copy of inputs ==
__global__ void k_logits(const float* __restrict__ inputs,
                         const float* __restrict__ W,
                         float* __restrict__ logits,
                         __half* __restrict__ inh) {
    extern __shared__ float Wt[];   // [16][1024]
    int tid = threadIdx.x;
    for (int idx = tid; idx < DD * HH; idx += 256) {
        int i = idx >> 4, h = idx & 15;
        Wt[h * DD + i] = W[idx];
    }
    __syncthreads();
    int warp = tid >> 5, lane = tid & 31;
    for (int rr = 0; rr < 4; rr++) {
        int r = blockIdx.x * 32 + warp * 4 + rr;
        const float4* xp = (const float4*)(inputs + (size_t)r * DD);
        uint2* hp = (uint2*)(inh + (size_t)r * DD);
        float acc[HH];
        #pragma unroll
        for (int h = 0; h < HH; h++) acc[h] = 0.f;
        #pragma unroll
        for (int j = 0; j < 8; j++) {
            float4 x = xp[lane + 32 * j];
            hp[lane + 32 * j] = make_uint2(pack_h2(x.x, x.y), pack_h2(x.z, x.w));
            int i0 = (lane + 32 * j) * 4;
            #pragma unroll
            for (int h = 0; h < HH; h++) {
                float4 w = *(const float4*)&Wt[h * DD + i0];
                acc[h] += x.x * w.x + x.y * w.y + x.z * w.z + x.w * w.w;
            }
        }
        #pragma unroll
        for (int h = 0; h < HH; h++) {
            #pragma unroll
            for (int o = 16; o > 0; o >>= 1)
                acc[h] += __shfl_xor_sync(0xffffffffu, acc[h], o);
        }
        if (lane == 0) {
            #pragma unroll
            for (int h = 0; h < HH; h++) logits[(size_t)r * HH + h] = acc[h];
        }
    }
}

// ------------- per (b,h): max over S, then att = exp((x-max)*temp) -------
__global__ void k_att_norm(float* __restrict__ logits, const float* __restrict__ temp) {
    int b = blockIdx.x >> 4, h = blockIdx.x & 15;
    float* p = logits + (size_t)b * SS * HH + h;
    float m = -3.4e38f;
    for (int s = threadIdx.x; s < SS; s += 256) m = fmaxf(m, p[(size_t)s * HH]);
    __shared__ float red[256];
    red[threadIdx.x] = m; __syncthreads();
    for (int o = 128; o > 0; o >>= 1) {
        if (threadIdx.x < o) red[threadIdx.x] = fmaxf(red[threadIdx.x], red[threadIdx.x + o]);
        __syncthreads();
    }
    m = red[0];
    float t = temp[h];
    for (int s = threadIdx.x; s < SS; s += 256) {
        size_t idx = (size_t)s * HH;
        p[idx] = expf((p[idx] - m) * t);
    }
}

// ---------------- scans (scan1 now fused into v-GEMM) -------------------
#define DD4 (DD/4)
__global__ void k_scan2(float4* __restrict__ segsum) {
    int b = blockIdx.x, c = threadIdx.x;
    float4 run = make_float4(0.f, 0.f, 0.f, 0.f);
    for (int seg = 0; seg < NSEG; seg++) {
        size_t idx = ((size_t)b * NSEG + seg) * DD4 + c;
        float4 v = segsum[idx];
        segsum[idx] = run;
        run.x += v.x; run.y += v.y; run.z += v.z; run.w += v.w;
    }
}

// prefix + att scaling; writes attn_out as half
__global__ void k_scan3(const float4* __restrict__ V, const float4* __restrict__ segsum,
                        const float* __restrict__ att, __half* __restrict__ out) {
    int c = blockIdx.x * 128 + threadIdx.x;
    int seg = blockIdx.y, b = blockIdx.z;
    int h = c >> 4;            // 16 float4 groups per head
    float4 run = segsum[((size_t)b * NSEG + seg) * DD4 + c];
    size_t base = (size_t)b * SS + (size_t)seg * SEG;
    const float4* p = V + base * DD4 + c;
    const float* ap = att + base * HH + h;
    __half* op = out + base * DD + c * 4;
    #pragma unroll 4
    for (int i = 0; i < SEG; i++) {
        float4 v = p[(size_t)i * DD4];
        run.x += v.x; run.y += v.y; run.z += v.z; run.w += v.w;
        float a = ap[(size_t)i * HH];
        float cnt = (float)(seg * SEG + i + 1);
        float s = a / (a * cnt + 1e-30f);
        *(uint32_t*)(op + (size_t)i * DD)     = pack_h2(run.x * s, run.y * s);
        *(uint32_t*)(op + (size_t)i * DD + 2) = pack_h2(run.z * s, run.w * s);
    }
}

// ---------------- LayerNorm (in place over d_out rows) ------------------
__global__ void k_ln(float* __restrict__ X, const float* __restrict__ g,
                     const float* __restrict__ be) {
    int r = blockIdx.x;
    float* p = X + (size_t)r * DD;
    int i = threadIdx.x * 4;
    float4 x = *(const float4*)(p + i);
    __shared__ float red[256];
    float s = x.x + x.y + x.z + x.w;
    red[threadIdx.x] = s; __syncthreads();
    for (int o = 128; o > 0; o >>= 1) {
        if (threadIdx.x < o) red[threadIdx.x] += red[threadIdx.x + o];
        __syncthreads();
    }
    float mean = red[0] * (1.f / DD);
    __syncthreads();
    float d0 = x.x - mean, d1 = x.y - mean, d2 = x.z - mean, d3 = x.w - mean;
    red[threadIdx.x] = d0 * d0 + d1 * d1 + d2 * d2 + d3 * d3;
    __syncthreads();
    for (int o = 128; o > 0; o >>= 1) {
        if (threadIdx.x < o) red[threadIdx.x] += red[threadIdx.x + o];
        __syncthreads();
    }
    float inv = rsqrtf(red[0] * (1.f / DD) + 1e-6f);
    float4 o4;
    o4.x = d0 * inv * g[i + 0] + be[i + 0];
    o4.y = d1 * inv * g[i + 1] + be[i + 1];
    o4.z = d2 * inv * g[i + 2] + be[i + 2];
    o4.w = d3 * inv * g[i + 3] + be[i + 3];
    *(float4*)(p + i) = o4;
}

// ---------------- launcher ----------------------------------------------
extern "C" void kernel_launch(void* const* d_in, const int* in_sizes, int n_in,
                              void* d_out, int out_size) {
    (void)in_sizes; (void)n_in; (void)out_size;
    const float* inputs   = (const float*)d_in[0];
    const float* vector   = (const float*)d_in[1];
    const float* attw     = (const float*)d_in[2];
    const float* temp     = (const float*)d_in[3];
    const float* values   = (const float*)d_in[4];
    const float* oper     = (const float*)d_in[5];
    const float* ff1      = (const float*)d_in[6];
    const float* ff1_bias = (const float*)d_in[7];
    const float* ff2      = (const float*)d_in[8];
    const float* ff2_bias = (const float*)d_in[9];
    const float* ln_gamma = (const float*)d_in[10];
    const float* ln_beta  = (const float*)d_in[11];
    float* out = (float*)d_out;

    float *att_p, *v_p, *seg_p, *vb_p;
    __half *inh_p, *attnh_p, *h1h_p, *valT_p, *f1tT_p, *t1_p, *ff2T_p, *operh_p, *owT_p;
    cudaGetSymbolAddress((void**)&att_p,   g_att);
    cudaGetSymbolAddress((void**)&v_p,     g_v);
    cudaGetSymbolAddress((void**)&seg_p,   g_seg);
    cudaGetSymbolAddress((void**)&vb_p,    g_vb);
    cudaGetSymbolAddress((void**)&inh_p,   g_in_h);
    cudaGetSymbolAddress((void**)&attnh_p, g_attn_h);
    cudaGetSymbolAddress((void**)&h1h_p,   g_h1h);
    cudaGetSymbolAddress((void**)&valT_p,  g_valTh);
    cudaGetSymbolAddress((void**)&f1tT_p,  g_f1tTh);
    cudaGetSymbolAddress((void**)&t1_p,    g_t1h);
    cudaGetSymbolAddress((void**)&ff2T_p,  g_ff2Th);
    cudaGetSymbolAddress((void**)&operh_p, g_operh);
    cudaGetSymbolAddress((void**)&owT_p,   g_owTh);

    cudaFuncSetAttribute(gemm_mma<1>, cudaFuncAttributeMaxDynamicSharedMemorySize, GEMM_SMEM);
    cudaFuncSetAttribute(gemm_mma<2>, cudaFuncAttributeMaxDynamicSharedMemorySize, GEMM_SMEM);
    cudaFuncSetAttribute(gemm_mma<3>, cudaFuncAttributeMaxDynamicSharedMemorySize, GEMM_SMEM);
    cudaFuncSetAttribute(gemm_mma<4>, cudaFuncAttributeMaxDynamicSharedMemorySize, GEMM_SMEM);
    cudaFuncSetAttribute(k_logits, cudaFuncAttributeMaxDynamicSharedMemorySize, 65536);

    dim3 tb(32, 8), tg(32, 32);
    k_transpose_h<<<tg, tb>>>(values, valT_p);
    k_transpose_h<<<tg, tb>>>(ff1, f1tT_p);
    k_transpose_h<<<tg, tb>>>(ff1 + (size_t)DD * DD, t1_p);
    k_transpose_h<<<tg, tb>>>(ff2, ff2T_p);
    k_cvt_h<<<(DD * DD / 4 + 255) / 256, 256>>>(oper, operh_p, DD * DD / 4);

    k_vb<<<dim3(DD / 256, BB), 256>>>(vector, t1_p, ff1_bias, vb_p);

    // owT[n][f] = sum_dv t1[n][dv] * operator[f][dv]  (half out)
    gemm_mma<1><<<dim3(8, 8), 256, GEMM_SMEM>>>(t1_p, operh_p, nullptr, nullptr,
                                                owT_p, nullptr, nullptr);

    // logits (+ half copy of inputs), att normalization
    k_logits<<<MR / 32, 256, 65536>>>(inputs, attw, att_p, inh_p);
    k_att_norm<<<BB * HH, 256>>>(att_p, temp);

    // v = inputs @ values (fp32 out) + fused segment sums (scan pass 1)
    gemm_mma<4><<<dim3(8, MR / 128), 256, GEMM_SMEM>>>(inh_p, valT_p, nullptr, nullptr,
                                                       v_p, seg_p, nullptr);

    // causal cumsum + att scaling -> half attn_out
    k_scan2<<<BB, 256>>>((float4*)seg_p);
    dim3 scanGrid(2, NSEG, BB);
    k_scan3<<<scanGrid, 128>>>((const float4*)v_p, (const float4*)seg_p, att_p, attnh_p);

    // h1 = relu(inputs@ff1_top + attn@OW + vb)  (half out)
    gemm_mma<2><<<dim3(8, MR / 128), 256, GEMM_SMEM>>>(inh_p, f1tT_p, attnh_p, owT_p,
                                                       h1h_p, nullptr, vb_p);

    // out = h1 @ ff2 + b2 + inputs (fp32)
    gemm_mma<3><<<dim3(8, MR / 128), 256, GEMM_SMEM>>>(h1h_p, ff2T_p, nullptr, nullptr,
                                                       out, (float*)inputs, ff2_bias);

    k_ln<<<MR, 256>>>(out, ln_gamma, ln_beta);
}